// round 9
// baseline (speedup 1.0000x reference)
#include <cuda_runtime.h>
#include <cstdint>

#define L_NUM 63
#define THREADS 448
#define SAMP_PER_CTA 896

// compact block index: S(l) = number of (layer,dpair) 64B blocks before layer l
__host__ __device__ __forceinline__ constexpr int S_blk(int l) {
    int m = l >> 1;
    return (l & 1) ? (m + 1) * (m + 1) : m * (m + 1);
}
#define NBLK 1024
#define WT_FLOATS (NBLK * 16)   // 64 KB weight table in smem

__device__ float  g_Wt[WT_FLOATS];
__device__ float2 g_W2p[L_NUM * 8];

// masked / transposed / d-pair-interleaved compact weight table
__global__ void prep_kernel(const float* __restrict__ W1, const float* __restrict__ W2) {
    int i = blockIdx.x * blockDim.x + threadIdx.x;
    if (i < 63 * 32 * 16) {
        int p  = i & 1;
        int h  = (i >> 1) & 7;
        int dp = (i >> 4) & 31;
        int l  = i >> 9;
        if (dp <= (l >> 1)) {
            int d = 2 * dp + p;
            float v = (d <= l) ? W1[l * 504 + h * 63 + d] : 0.0f;
            g_Wt[(S_blk(l) + dp) * 16 + h * 2 + p] = v;
        }
    } else {
        int j = i - 63 * 32 * 16;
        if (j < L_NUM * 8) {
            int l = j >> 3, h = j & 7;
            g_W2p[j] = make_float2(W2[l * 16 + h], W2[l * 16 + 8 + h]);
        }
    }
}

__device__ __forceinline__ unsigned long long fma2(unsigned long long a,
                                                   unsigned long long b,
                                                   unsigned long long c) {
    unsigned long long d;
    asm("fma.rn.f32x2 %0, %1, %2, %3;" : "=l"(d) : "l"(a), "l"(b), "l"(c));
    return d;
}
__device__ __forceinline__ void unpack2(unsigned long long v, float& lo, float& hi) {
    asm("mov.b64 {%0, %1}, %2;" : "=f"(lo), "=f"(hi) : "l"(v));
}
__device__ __forceinline__ unsigned long long pack2(float lo, float hi) {
    unsigned long long v;
    asm("mov.b64 %0, {%1, %2};" : "=l"(v) : "f"(lo), "f"(hi));
    return v;
}
__device__ __forceinline__ unsigned long long dup2(float f) {
    unsigned long long v;
    asm("mov.b64 %0, {%1, %1};" : "=l"(v) : "f"(f));
    return v;
}
__device__ __forceinline__ float tanh_fast(float a) {
    float y; asm("tanh.approx.f32 %0, %1;" : "=f"(y) : "f"(a)); return y;
}
__device__ __forceinline__ float exp_fast(float a) {
    float y; asm("ex2.approx.f32 %0, %1;" : "=f"(y) : "f"(a * 1.442695041f)); return y;
}

// SMEM float offsets
#define OFF_B1  16384           // 504 floats
#define OFF_W2P 16888           // u64[504] (byte 67552, 8B aligned)
#define OFF_B2  17896           // 126 floats
#define OFF_XB  18024           // 448 rows x 66 floats (row base 264B -> 8B aligned)
#define XB_STRIDE 66
#define SMEM_FLOATS (18024 + THREADS * XB_STRIDE)

__global__ __launch_bounds__(THREADS, 1)
void flow_kernel(const float* __restrict__ x,
                 const float* __restrict__ ipar,
                 const float* __restrict__ b1g,
                 const float* __restrict__ b2g,
                 float* __restrict__ z_out,
                 float* __restrict__ ld_out,
                 int B, int has_ld)
{
    extern __shared__ float smem[];
    const int tid = threadIdx.x;
    const int base = blockIdx.x * SAMP_PER_CTA;

    const int sA = base + tid;                 // register-resident sample
    const int sB = base + THREADS + tid;       // smem-resident sample
    const bool validA = sA < B;
    const bool validB = sB < B;

    // ---- cooperative SMEM fill: weights + epilogue tables ----
    {
        const float4* src = (const float4*)g_Wt;
        float4* dst = (float4*)smem;
        for (int i = tid; i < WT_FLOATS / 4; i += THREADS) dst[i] = src[i];
        for (int i = tid; i < 504; i += THREADS) smem[OFF_B1 + i] = b1g[i];
        unsigned long long* w2d = (unsigned long long*)(smem + OFF_W2P);
        const unsigned long long* w2s = (const unsigned long long*)g_W2p;
        for (int i = tid; i < 504; i += THREADS) w2d[i] = w2s[i];
        for (int i = tid; i < 126; i += THREADS) smem[OFF_B2 + i] = b2g[i];
    }
    // ---- stage B-half x rows: coalesced global -> padded smem rows ----
    {
        const int nBrows = min(THREADS, max(0, B - (base + THREADS)));
        const float2* xg = (const float2*)(x + (size_t)(base + THREADS) * 64);
        #pragma unroll
        for (int k = 0; k < 32; k++) {
            int idx = tid + k * THREADS;       // 0 .. 448*32-1
            int row = idx >> 5, c2 = idx & 31;
            if (row < nBrows) {
                float2 v = xg[idx];
                *(float2*)&smem[OFF_XB + row * XB_STRIDE + 2 * c2] = v;
            }
        }
    }
    // ---- A-half x row straight into registers (per-thread LDG.128 x16) ----
    unsigned long long xpA[32];
    {
        const ulonglong2* xr = (const ulonglong2*)(x + (size_t)(validA ? sA : base) * 64);
        #pragma unroll
        for (int i = 0; i < 16; i++) {
            ulonglong2 v = xr[i];
            xpA[2 * i] = v.x; xpA[2 * i + 1] = v.y;
        }
    }
    __syncthreads();

    const float mu0 = ipar[0];
    const float al0 = ipar[1];
    const float e0  = exp_fast(al0);
    float ldA = al0, ldB = al0;

    float* zA = z_out + (size_t)sA * 64;
    float* zB = z_out + (size_t)sB * 64;
    const float* xbrow = smem + OFF_XB + tid * XB_STRIDE;

    float zHoldA, zHoldB;
    {
        float a0, a1; unpack2(xpA[0], a0, a1);
        zHoldA = a0 * e0 + mu0;
        zHoldB = xbrow[0] * e0 + mu0;
    }

    const ulonglong2* wbase = (const ulonglong2*)smem;   // 4 x 16B per (l,dp) block

    #pragma unroll
    for (int l = 0; l < L_NUM; l++) {
        unsigned long long accA[8], accB[8];
        #pragma unroll
        for (int j = 0; j < 8; j++) { accA[j] = 0ull; accB[j] = 0ull; }

        const int ndp = (l >> 1) + 1;
        const ulonglong2* wb = wbase + S_blk(l) * 4;
        #pragma unroll
        for (int dp = 0; dp < ndp; dp++) {
            ulonglong2 w01 = wb[dp * 4 + 0];
            ulonglong2 w23 = wb[dp * 4 + 1];
            ulonglong2 w45 = wb[dp * 4 + 2];
            ulonglong2 w67 = wb[dp * 4 + 3];
            unsigned long long xa = xpA[dp];
            unsigned long long xb = *(const unsigned long long*)&xbrow[2 * dp];
            accA[0] = fma2(xa, w01.x, accA[0]);  accB[0] = fma2(xb, w01.x, accB[0]);
            accA[1] = fma2(xa, w01.y, accA[1]);  accB[1] = fma2(xb, w01.y, accB[1]);
            accA[2] = fma2(xa, w23.x, accA[2]);  accB[2] = fma2(xb, w23.x, accB[2]);
            accA[3] = fma2(xa, w23.y, accA[3]);  accB[3] = fma2(xb, w23.y, accB[3]);
            accA[4] = fma2(xa, w45.x, accA[4]);  accB[4] = fma2(xb, w45.x, accB[4]);
            accA[5] = fma2(xa, w45.y, accA[5]);  accB[5] = fma2(xb, w45.y, accB[5]);
            accA[6] = fma2(xa, w67.x, accA[6]);  accB[6] = fma2(xb, w67.x, accB[6]);
            accA[7] = fma2(xa, w67.y, accA[7]);  accB[7] = fma2(xb, w67.y, accB[7]);
        }

        // reduce + bias + tanh; layer-2 as packed (mu, alpha) f32x2
        unsigned long long maA, maB;
        {
            float m0 = smem[OFF_B2 + 2 * l], a0 = smem[OFF_B2 + 2 * l + 1];
            unsigned long long init = pack2(m0, a0);
            maA = init; maB = init;
        }
        const unsigned long long* w2p = (const unsigned long long*)(smem + OFF_W2P) + l * 8;
        #pragma unroll
        for (int j = 0; j < 8; j++) {
            float bb = smem[OFF_B1 + l * 8 + j];
            float loA, hiA, loB, hiB;
            unpack2(accA[j], loA, hiA);
            unpack2(accB[j], loB, hiB);
            float hA = tanh_fast(loA + hiA + bb);
            float hB = tanh_fast(loB + hiB + bb);
            unsigned long long w2 = w2p[j];
            maA = fma2(dup2(hA), w2, maA);
            maB = fma2(dup2(hB), w2, maB);
        }
        float muA, alA, muB, alB;
        unpack2(maA, muA, alA);
        unpack2(maB, muB, alB);
        ldA += alA; ldB += alB;

        float xnA, xnB;
        {
            float lo, hi;
            unpack2(xpA[(l + 1) >> 1], lo, hi);
            xnA = ((l + 1) & 1) ? hi : lo;
        }
        xnB = xbrow[l + 1];
        float znA = xnA * exp_fast(alA) + muA;
        float znB = xnB * exp_fast(alB) + muB;

        if (l & 1) {            // odd layer: hold z[l+1] (even index)
            zHoldA = znA;
            zHoldB = znB;
        } else {                // even layer: store aligned pair (z[l], z[l+1])
            if (validA) *(unsigned long long*)(zA + l) = pack2(zHoldA, znA);
            if (validB) *(unsigned long long*)(zB + l) = pack2(zHoldB, znB);
        }
    }

    if (has_ld) {
        if (validA) ld_out[sA] = ldA;
        if (validB) ld_out[sB] = ldB;
    }
}

extern "C" void kernel_launch(void* const* d_in, const int* in_sizes, int n_in,
                              void* d_out, int out_size) {
    const float* x  = (const float*)d_in[0];
    const float* ip = (const float*)d_in[1];
    const float* W1 = (const float*)d_in[2];
    const float* b1 = (const float*)d_in[3];
    const float* W2 = (const float*)d_in[4];
    const float* b2 = (const float*)d_in[5];

    int B = in_sizes[0] / 64;
    float* z   = (float*)d_out;
    float* ldp = z + (size_t)B * 64;
    int has_ld = (out_size >= B * 64 + B) ? 1 : 0;

    size_t smem = (size_t)SMEM_FLOATS * sizeof(float);
    cudaFuncSetAttribute(flow_kernel, cudaFuncAttributeMaxDynamicSharedMemorySize, (int)smem);

    int prep_n = 63 * 32 * 16 + L_NUM * 8;
    prep_kernel<<<(prep_n + 255) / 256, 256>>>(W1, W2);

    int grid = (B + SAMP_PER_CTA - 1) / SAMP_PER_CTA;   // 147 for B=131072 -> single wave
    flow_kernel<<<grid, THREADS, smem>>>(x, ip, b1, b2, z, ldp, B, has_ld);
}

// round 10
// speedup vs baseline: 1.0408x; 1.0408x over previous
#include <cuda_runtime.h>
#include <cstdint>

#define L_NUM 63
#define THREADS 448
#define SAMP_PER_CTA 896

// compact block index: S(l) = number of (layer,dpair) 64B blocks before layer l
__host__ __device__ __forceinline__ constexpr int S_blk(int l) {
    int m = l >> 1;
    return (l & 1) ? (m + 1) * (m + 1) : m * (m + 1);
}
#define NBLK 1024
#define WT_FLOATS (NBLK * 16)   // 64 KB weight table in smem

__device__ float  g_Wt[WT_FLOATS];
__device__ float2 g_W2p[L_NUM * 8];

// masked / transposed / d-pair-interleaved compact weight table
__global__ void prep_kernel(const float* __restrict__ W1, const float* __restrict__ W2) {
    int i = blockIdx.x * blockDim.x + threadIdx.x;
    if (i < 63 * 32 * 16) {
        int p  = i & 1;
        int h  = (i >> 1) & 7;
        int dp = (i >> 4) & 31;
        int l  = i >> 9;
        if (dp <= (l >> 1)) {
            int d = 2 * dp + p;
            float v = (d <= l) ? W1[l * 504 + h * 63 + d] : 0.0f;
            g_Wt[(S_blk(l) + dp) * 16 + h * 2 + p] = v;
        }
    } else {
        int j = i - 63 * 32 * 16;
        if (j < L_NUM * 8) {
            int l = j >> 3, h = j & 7;
            g_W2p[j] = make_float2(W2[l * 16 + h], W2[l * 16 + 8 + h]);
        }
    }
}

__device__ __forceinline__ unsigned long long fma2(unsigned long long a,
                                                   unsigned long long b,
                                                   unsigned long long c) {
    unsigned long long d;
    asm("fma.rn.f32x2 %0, %1, %2, %3;" : "=l"(d) : "l"(a), "l"(b), "l"(c));
    return d;
}
__device__ __forceinline__ void unpack2(unsigned long long v, float& lo, float& hi) {
    asm("mov.b64 {%0, %1}, %2;" : "=f"(lo), "=f"(hi) : "l"(v));
}
__device__ __forceinline__ unsigned long long pack2(float lo, float hi) {
    unsigned long long v;
    asm("mov.b64 %0, {%1, %2};" : "=l"(v) : "f"(lo), "f"(hi));
    return v;
}
__device__ __forceinline__ unsigned long long dup2(float f) {
    unsigned long long v;
    asm("mov.b64 %0, {%1, %1};" : "=l"(v) : "f"(f));
    return v;
}
__device__ __forceinline__ float tanh_fast(float a) {
    float y; asm("tanh.approx.f32 %0, %1;" : "=f"(y) : "f"(a)); return y;
}
__device__ __forceinline__ float exp_fast(float a) {
    float y; asm("ex2.approx.f32 %0, %1;" : "=f"(y) : "f"(a * 1.442695041f)); return y;
}

// SMEM float offsets
#define OFF_B1  16384           // 504 floats
#define OFF_W2P 16888           // u64[504] (byte 67552, 8B aligned)
#define OFF_B2  17896           // 126 floats
#define OFF_XB  18024           // 448 rows x 66 floats (row base 264B -> 8B aligned)
#define XB_STRIDE 66
#define SMEM_FLOATS (18024 + THREADS * XB_STRIDE)   // 47592 floats = 190368 B

__global__ __launch_bounds__(THREADS, 1)
void flow_kernel(const float* __restrict__ x,
                 const float* __restrict__ ipar,
                 const float* __restrict__ b1g,
                 const float* __restrict__ b2g,
                 float* __restrict__ z_out,
                 float* __restrict__ ld_out,
                 int B, int has_ld)
{
    extern __shared__ float smem[];
    const int tid = threadIdx.x;
    const int base = blockIdx.x * SAMP_PER_CTA;

    const int sA = base + tid;                 // register-resident sample
    const int sB = base + THREADS + tid;       // smem-resident sample
    const bool validA = sA < B;
    const bool validB = sB < B;

    // ---- cooperative SMEM fill: weights + epilogue tables ----
    {
        const float4* src = (const float4*)g_Wt;
        float4* dst = (float4*)smem;
        for (int i = tid; i < WT_FLOATS / 4; i += THREADS) dst[i] = src[i];
        for (int i = tid; i < 504; i += THREADS) smem[OFF_B1 + i] = b1g[i];
        unsigned long long* w2d = (unsigned long long*)(smem + OFF_W2P);
        const unsigned long long* w2s = (const unsigned long long*)g_W2p;
        for (int i = tid; i < 504; i += THREADS) w2d[i] = w2s[i];
        for (int i = tid; i < 126; i += THREADS) smem[OFF_B2 + i] = b2g[i];
    }
    // ---- stage B-half x rows: coalesced global -> padded smem rows ----
    {
        const int nBrows = min(THREADS, max(0, B - (base + THREADS)));
        const float2* xg = (const float2*)(x + (size_t)(base + THREADS) * 64);
        #pragma unroll
        for (int k = 0; k < 32; k++) {
            int idx = tid + k * THREADS;       // 0 .. 448*32-1
            int row = idx >> 5, c2 = idx & 31;
            if (row < nBrows) {
                float2 v = xg[idx];
                *(float2*)&smem[OFF_XB + row * XB_STRIDE + 2 * c2] = v;
            }
        }
    }
    // ---- A-half x row straight into registers (per-thread LDG.128 x16) ----
    unsigned long long xpA[32];
    {
        const ulonglong2* xr = (const ulonglong2*)(x + (size_t)(validA ? sA : base) * 64);
        #pragma unroll
        for (int i = 0; i < 16; i++) {
            ulonglong2 v = xr[i];
            xpA[2 * i] = v.x; xpA[2 * i + 1] = v.y;
        }
    }
    __syncthreads();

    const float mu0 = ipar[0];
    const float al0 = ipar[1];
    const float e0  = exp_fast(al0);
    float ldA = al0, ldB = al0;

    float* zA = z_out + (size_t)sA * 64;
    float* zB = z_out + (size_t)sB * 64;
    const float* xbrow = smem + OFF_XB + tid * XB_STRIDE;

    // z accumulated 4-wide in regs; one aligned STG.128 per 4 layers
    float zqA[4], zqB[4];
    {
        float a0, a1; unpack2(xpA[0], a0, a1);
        zqA[0] = a0 * e0 + mu0;
        zqB[0] = xbrow[0] * e0 + mu0;
    }

    const ulonglong2* wbase = (const ulonglong2*)smem;   // 4 x 16B per (l,dp) block

    #pragma unroll
    for (int l = 0; l < L_NUM; l++) {
        unsigned long long accA[8], accB[8];
        #pragma unroll
        for (int j = 0; j < 8; j++) { accA[j] = 0ull; accB[j] = 0ull; }

        const int ndp = (l >> 1) + 1;
        const ulonglong2* wb = wbase + S_blk(l) * 4;
        #pragma unroll
        for (int dp = 0; dp < ndp; dp++) {
            ulonglong2 w01 = wb[dp * 4 + 0];
            ulonglong2 w23 = wb[dp * 4 + 1];
            ulonglong2 w45 = wb[dp * 4 + 2];
            ulonglong2 w67 = wb[dp * 4 + 3];
            unsigned long long xa = xpA[dp];
            unsigned long long xb = *(const unsigned long long*)&xbrow[2 * dp];
            accA[0] = fma2(xa, w01.x, accA[0]);  accB[0] = fma2(xb, w01.x, accB[0]);
            accA[1] = fma2(xa, w01.y, accA[1]);  accB[1] = fma2(xb, w01.y, accB[1]);
            accA[2] = fma2(xa, w23.x, accA[2]);  accB[2] = fma2(xb, w23.x, accB[2]);
            accA[3] = fma2(xa, w23.y, accA[3]);  accB[3] = fma2(xb, w23.y, accB[3]);
            accA[4] = fma2(xa, w45.x, accA[4]);  accB[4] = fma2(xb, w45.x, accB[4]);
            accA[5] = fma2(xa, w45.y, accA[5]);  accB[5] = fma2(xb, w45.y, accB[5]);
            accA[6] = fma2(xa, w67.x, accA[6]);  accB[6] = fma2(xb, w67.x, accB[6]);
            accA[7] = fma2(xa, w67.y, accA[7]);  accB[7] = fma2(xb, w67.y, accB[7]);
        }

        // reduce + bias + tanh; layer-2 as packed (mu, alpha) f32x2
        unsigned long long maA, maB;
        {
            float m0 = smem[OFF_B2 + 2 * l], a0 = smem[OFF_B2 + 2 * l + 1];
            unsigned long long init = pack2(m0, a0);
            maA = init; maB = init;
        }
        const unsigned long long* w2p = (const unsigned long long*)(smem + OFF_W2P) + l * 8;
        #pragma unroll
        for (int j = 0; j < 8; j++) {
            float bb = smem[OFF_B1 + l * 8 + j];
            float loA, hiA, loB, hiB;
            unpack2(accA[j], loA, hiA);
            unpack2(accB[j], loB, hiB);
            float hA = tanh_fast(loA + hiA + bb);
            float hB = tanh_fast(loB + hiB + bb);
            unsigned long long w2 = w2p[j];
            maA = fma2(dup2(hA), w2, maA);
            maB = fma2(dup2(hB), w2, maB);
        }
        float muA, alA, muB, alB;
        unpack2(maA, muA, alA);
        unpack2(maB, muB, alB);
        ldA += alA; ldB += alB;

        float xnA;
        {
            float lo, hi;
            unpack2(xpA[(l + 1) >> 1], lo, hi);
            xnA = ((l + 1) & 1) ? hi : lo;
        }
        float xnB = xbrow[l + 1];

        const int zi = l + 1;                 // z index produced this layer
        zqA[zi & 3] = xnA * exp_fast(alA) + muA;
        zqB[zi & 3] = xnB * exp_fast(alB) + muB;

        if ((zi & 3) == 3) {                  // flush aligned quad z[zi-3 .. zi]
            if (validA)
                *(float4*)(zA + (zi - 3)) = make_float4(zqA[0], zqA[1], zqA[2], zqA[3]);
            if (validB)
                *(float4*)(zB + (zi - 3)) = make_float4(zqB[0], zqB[1], zqB[2], zqB[3]);
        }
    }

    if (has_ld) {
        if (validA) ld_out[sA] = ldA;
        if (validB) ld_out[sB] = ldB;
    }
}

extern "C" void kernel_launch(void* const* d_in, const int* in_sizes, int n_in,
                              void* d_out, int out_size) {
    const float* x  = (const float*)d_in[0];
    const float* ip = (const float*)d_in[1];
    const float* W1 = (const float*)d_in[2];
    const float* b1 = (const float*)d_in[3];
    const float* W2 = (const float*)d_in[4];
    const float* b2 = (const float*)d_in[5];

    int B = in_sizes[0] / 64;
    float* z   = (float*)d_out;
    float* ldp = z + (size_t)B * 64;
    int has_ld = (out_size >= B * 64 + B) ? 1 : 0;

    size_t smem = (size_t)SMEM_FLOATS * sizeof(float);
    cudaFuncSetAttribute(flow_kernel, cudaFuncAttributeMaxDynamicSharedMemorySize, (int)smem);

    int prep_n = 63 * 32 * 16 + L_NUM * 8;
    prep_kernel<<<(prep_n + 255) / 256, 256>>>(W1, W2);

    int grid = (B + SAMP_PER_CTA - 1) / SAMP_PER_CTA;   // 147 for B=131072 -> single wave
    flow_kernel<<<grid, THREADS, smem>>>(x, ip, b1, b2, z, ldp, B, has_ld);
}

// round 11
// speedup vs baseline: 1.7141x; 1.6468x over previous
#include <cuda_runtime.h>
#include <cstdint>

#define L_NUM 63
#define THREADS 224

// compact block index: S(l) = number of (layer,dpair) blocks before layer l
__host__ __device__ __forceinline__ constexpr int S_blk(int l) {
    int m = l >> 1;
    return (l & 1) ? (m + 1) * (m + 1) : m * (m + 1);
}
#define NBLK 1024

// staging tables written by prep kernel
__device__ ulonglong2 g_lo[NBLK * 2];   // h0..h3 per block  (32 KB)
__device__ ulonglong2 g_hi[NBLK * 2];   // h4..h7 per block  (32 KB)
__device__ float g_B1[504];
__device__ unsigned long long g_W2p[504];
__device__ float g_B2[126];

// constant-memory copies (separate port from the smem crossbar)
__constant__ ulonglong2 c_Wlo[NBLK * 2];          // 32 KB
__constant__ float c_B1[504];
__constant__ unsigned long long c_W2p[504];
__constant__ float c_B2[126];

// masked / transposed / d-pair-interleaved compact weight tables (split by h half)
__global__ void prep_kernel(const float* __restrict__ W1, const float* __restrict__ W2,
                            const float* __restrict__ b1, const float* __restrict__ b2) {
    int i = blockIdx.x * blockDim.x + threadIdx.x;
    if (i < 63 * 32 * 16) {
        int p  = i & 1;
        int h  = (i >> 1) & 7;
        int dp = (i >> 4) & 31;
        int l  = i >> 9;
        if (dp <= (l >> 1)) {
            int d = 2 * dp + p;
            float v = (d <= l) ? W1[l * 504 + h * 63 + d] : 0.0f;
            int blk = S_blk(l) + dp;
            float* tbl = (h < 4) ? (float*)g_lo : (float*)g_hi;
            int hh = h & 3;
            tbl[blk * 8 + hh * 2 + p] = v;
        }
    } else {
        int j = i - 63 * 32 * 16;
        if (j < 504) {
            int l = j >> 3, h = j & 7;
            float2 w = make_float2(W2[l * 16 + h], W2[l * 16 + 8 + h]);
            g_W2p[j] = *(unsigned long long*)&w;
            g_B1[j] = b1[j];
            if (j < 126) g_B2[j] = b2[j];
        }
    }
}

__device__ __forceinline__ unsigned long long fma2(unsigned long long a,
                                                   unsigned long long b,
                                                   unsigned long long c) {
    unsigned long long d;
    asm("fma.rn.f32x2 %0, %1, %2, %3;" : "=l"(d) : "l"(a), "l"(b), "l"(c));
    return d;
}
__device__ __forceinline__ void unpack2(unsigned long long v, float& lo, float& hi) {
    asm("mov.b64 {%0, %1}, %2;" : "=f"(lo), "=f"(hi) : "l"(v));
}
__device__ __forceinline__ unsigned long long dup2(float f) {
    unsigned long long v;
    asm("mov.b64 %0, {%1, %1};" : "=l"(v) : "f"(f));
    return v;
}
__device__ __forceinline__ float tanh_fast(float a) {
    float y; asm("tanh.approx.f32 %0, %1;" : "=f"(y) : "f"(a)); return y;
}
__device__ __forceinline__ float exp_fast(float a) {
    float y; asm("ex2.approx.f32 %0, %1;" : "=f"(y) : "f"(a * 1.442695041f)); return y;
}

// SMEM: [0, 32KB) hi-half weight table; then XZ rows 224 x 66 floats
#define OFF_XZ_F 8192
#define XZ_STRIDE 66
#define SMEM_FLOATS (8192 + THREADS * XZ_STRIDE)    // 22976 floats = 91904 B

__global__ __launch_bounds__(THREADS, 2)
void flow_kernel(const float* __restrict__ x,
                 const float* __restrict__ ipar,
                 float* __restrict__ z_out,
                 float* __restrict__ ld_out,
                 int B, int has_ld)
{
    extern __shared__ float smem[];
    const int tid = threadIdx.x;
    const int base = blockIdx.x * THREADS;
    const int validRows = min(THREADS, B - base);
    const bool valid = tid < validRows;

    // ---- fill hi-half weight table into smem (32 KB) ----
    {
        const float4* src = (const float4*)g_hi;
        float4* dst = (float4*)smem;
        for (int i = tid; i < 2048; i += THREADS) dst[i] = src[i];
    }
    // ---- stage x: coalesced global -> padded smem rows ----
    {
        const float2* xg = (const float2*)(x + (size_t)base * 64);
        #pragma unroll
        for (int k = 0; k < 32; k++) {
            int idx = tid + k * THREADS;        // 0 .. 224*32-1
            int row = idx >> 5, c2 = idx & 31;
            if (row < validRows) {
                float2 v = xg[idx];
                *(float2*)&smem[OFF_XZ_F + row * XZ_STRIDE + 2 * c2] = v;
            }
        }
    }
    __syncthreads();

    // ---- own x row into registers (32 u64 pairs) ----
    unsigned long long xp[32];
    #pragma unroll
    for (int i = 0; i < 32; i++)
        xp[i] = *(const unsigned long long*)&smem[OFF_XZ_F + tid * XZ_STRIDE + 2 * i];

    const float mu0 = ipar[0];
    const float al0 = ipar[1];
    float ld = al0;
    {
        float a0, a1; unpack2(xp[0], a0, a1);
        smem[OFF_XZ_F + tid * XZ_STRIDE + 0] = a0 * exp_fast(al0) + mu0;
    }

    const ulonglong2* sW = (const ulonglong2*)smem;   // hi-half table

    #pragma unroll
    for (int l = 0; l < L_NUM; l++) {
        unsigned long long acc[8];
        #pragma unroll
        for (int j = 0; j < 8; j++) acc[j] = 0ull;

        const int ndp = (l >> 1) + 1;
        #pragma unroll
        for (int dp = 0; dp < ndp; dp++) {
            const int blk = S_blk(l) + dp;      // compile-time after unroll
            ulonglong2 e0 = c_Wlo[blk * 2 + 0];   // const port: h0,h1
            ulonglong2 e1 = c_Wlo[blk * 2 + 1];   // const port: h2,h3
            ulonglong2 e2 = sW[blk * 2 + 0];      // smem port:  h4,h5
            ulonglong2 e3 = sW[blk * 2 + 1];      // smem port:  h6,h7
            unsigned long long xv = xp[dp];
            acc[0] = fma2(xv, e0.x, acc[0]);
            acc[1] = fma2(xv, e0.y, acc[1]);
            acc[2] = fma2(xv, e1.x, acc[2]);
            acc[3] = fma2(xv, e1.y, acc[3]);
            acc[4] = fma2(xv, e2.x, acc[4]);
            acc[5] = fma2(xv, e2.y, acc[5]);
            acc[6] = fma2(xv, e3.x, acc[6]);
            acc[7] = fma2(xv, e3.y, acc[7]);
        }

        // reduce + bias + tanh; layer-2 as packed (mu, alpha) f32x2 (const tables)
        unsigned long long ma;
        {
            float m0 = c_B2[2 * l], a0 = c_B2[2 * l + 1];
            asm("mov.b64 %0, {%1, %2};" : "=l"(ma) : "f"(m0), "f"(a0));
        }
        #pragma unroll
        for (int j = 0; j < 8; j++) {
            float lo, hi;
            unpack2(acc[j], lo, hi);
            float h = tanh_fast(lo + hi + c_B1[l * 8 + j]);
            ma = fma2(dup2(h), c_W2p[l * 8 + j], ma);
        }
        float mu, al;
        unpack2(ma, mu, al);
        ld += al;

        float xn;
        {
            float lo, hi;
            unpack2(xp[(l + 1) >> 1], lo, hi);
            xn = ((l + 1) & 1) ? hi : lo;
        }
        smem[OFF_XZ_F + tid * XZ_STRIDE + l + 1] = xn * exp_fast(al) + mu;
    }

    if (valid && has_ld) ld_out[base + tid] = ld;

    __syncthreads();
    // ---- coalesced z writeback ----
    {
        float2* zg = (float2*)(z_out + (size_t)base * 64);
        #pragma unroll
        for (int k = 0; k < 32; k++) {
            int idx = tid + k * THREADS;
            int row = idx >> 5, c2 = idx & 31;
            if (row < validRows) {
                float2 v = *(const float2*)&smem[OFF_XZ_F + row * XZ_STRIDE + 2 * c2];
                zg[idx] = v;
            }
        }
    }
}

extern "C" void kernel_launch(void* const* d_in, const int* in_sizes, int n_in,
                              void* d_out, int out_size) {
    const float* x  = (const float*)d_in[0];
    const float* ip = (const float*)d_in[1];
    const float* W1 = (const float*)d_in[2];
    const float* b1 = (const float*)d_in[3];
    const float* W2 = (const float*)d_in[4];
    const float* b2 = (const float*)d_in[5];

    int B = in_sizes[0] / 64;
    float* z   = (float*)d_out;
    float* ldp = z + (size_t)B * 64;
    int has_ld = (out_size >= B * 64 + B) ? 1 : 0;

    int prep_n = 63 * 32 * 16 + 512;
    prep_kernel<<<(prep_n + 255) / 256, 256>>>(W1, W2, b1, b2);

    // stage const tables (async D2D copies; graph-capturable)
    void* p = nullptr;
    cudaGetSymbolAddress(&p, g_lo);
    cudaMemcpyToSymbolAsync(c_Wlo, p, sizeof(g_lo), 0, cudaMemcpyDeviceToDevice);
    cudaGetSymbolAddress(&p, g_B1);
    cudaMemcpyToSymbolAsync(c_B1, p, sizeof(g_B1), 0, cudaMemcpyDeviceToDevice);
    cudaGetSymbolAddress(&p, g_W2p);
    cudaMemcpyToSymbolAsync(c_W2p, p, sizeof(g_W2p), 0, cudaMemcpyDeviceToDevice);
    cudaGetSymbolAddress(&p, g_B2);
    cudaMemcpyToSymbolAsync(c_B2, p, sizeof(g_B2), 0, cudaMemcpyDeviceToDevice);

    size_t smem = (size_t)SMEM_FLOATS * sizeof(float);
    cudaFuncSetAttribute(flow_kernel, cudaFuncAttributeMaxDynamicSharedMemorySize, (int)smem);

    int grid = (B + THREADS - 1) / THREADS;   // 586 for B=131072 -> ~99% wave efficiency
    flow_kernel<<<grid, THREADS, smem>>>(x, ip, z, ldp, B, has_ld);
}

// round 12
// speedup vs baseline: 2.0594x; 1.2015x over previous
#include <cuda_runtime.h>
#include <cuda_bf16.h>
#include <cstdint>

#define L_NUM  63
#define THREADS 512
#define TILE_M  256
#define NCHUNK  32            // 2 n-tiles (= 2 layers) per chunk

// fragment-layout weight tables: [0,8192) = Wh, [8192,16384) = Wl
// entry index = (nt*4 + kt)*32 + lane ; u64 = {b0 (lo32), b1 (hi32)}
__device__ unsigned long long g_Wfrag[16384];
__device__ float g_B1[504];
__device__ unsigned long long g_W2p[504];
__device__ float g_B2[126];

__constant__ float c_B1[504];
__constant__ unsigned long long c_W2p[504];
__constant__ float c_B2[126];

// Wg[k][n]: n = wcol = l*8+h (pad to 512), k = d; masked triangular
__global__ void prep_kernel(const float* __restrict__ W1, const float* __restrict__ W2,
                            const float* __restrict__ b1, const float* __restrict__ b2) {
    int i = blockIdx.x * blockDim.x + threadIdx.x;
    if (i < 8192) {
        int lane = i & 31;
        int kt   = (i >> 5) & 3;
        int nt   = i >> 7;
        int n  = nt * 8 + (lane >> 2);
        int k0 = kt * 16 + (lane & 3) * 2;
        int l = n >> 3, h = n & 7;
        int ks[4] = { k0, k0 + 1, k0 + 8, k0 + 9 };
        uint32_t bh[4], bl[4];
        #pragma unroll
        for (int j = 0; j < 4; j++) {
            int k = ks[j];
            float v = 0.0f;
            if (l < 63 && k <= l) v = W1[l * 504 + h * 63 + k];
            __nv_bfloat16 vh = __float2bfloat16_rn(v);
            float res = v - __bfloat162float(vh);
            __nv_bfloat16 vl = __float2bfloat16_rn(res);
            bh[j] = (uint32_t)__bfloat16_as_ushort(vh);
            bl[j] = (uint32_t)__bfloat16_as_ushort(vl);
        }
        // b0 = {k0 (lo), k0+1 (hi)}, b1 = {k0+8 (lo), k0+9 (hi)}
        uint32_t b0h = bh[0] | (bh[1] << 16), b1h = bh[2] | (bh[3] << 16);
        uint32_t b0l = bl[0] | (bl[1] << 16), b1l = bl[2] | (bl[3] << 16);
        g_Wfrag[i]        = (unsigned long long)b0h | ((unsigned long long)b1h << 32);
        g_Wfrag[8192 + i] = (unsigned long long)b0l | ((unsigned long long)b1l << 32);
    } else {
        int j = i - 8192;
        if (j < 504) {
            int l = j >> 3, h = j & 7;
            float2 w = make_float2(W2[l * 16 + h], W2[l * 16 + 8 + h]);
            g_W2p[j] = *(unsigned long long*)&w;
            g_B1[j] = b1[j];
            if (j < 126) g_B2[j] = b2[j];
        }
    }
}

// ---------------- helpers ----------------
__device__ __forceinline__ void mma_bf16(float* d, const uint32_t* a, uint32_t b0, uint32_t b1) {
    asm volatile(
        "mma.sync.aligned.m16n8k16.row.col.f32.bf16.bf16.f32 "
        "{%0,%1,%2,%3}, {%4,%5,%6,%7}, {%8,%9}, {%0,%1,%2,%3};"
        : "+f"(d[0]), "+f"(d[1]), "+f"(d[2]), "+f"(d[3])
        : "r"(a[0]), "r"(a[1]), "r"(a[2]), "r"(a[3]), "r"(b0), "r"(b1));
}
__device__ __forceinline__ uint32_t packbf(float lo, float hi) {
    uint32_t r;
    asm("cvt.rn.bf16x2.f32 %0, %1, %2;" : "=r"(r) : "f"(hi), "f"(lo));   // first src -> hi half
    return r;
}
__device__ __forceinline__ unsigned long long fma2(unsigned long long a,
                                                   unsigned long long b,
                                                   unsigned long long c) {
    unsigned long long d;
    asm("fma.rn.f32x2 %0, %1, %2, %3;" : "=l"(d) : "l"(a), "l"(b), "l"(c));
    return d;
}
__device__ __forceinline__ void unpack2(unsigned long long v, float& lo, float& hi) {
    asm("mov.b64 {%0, %1}, %2;" : "=f"(lo), "=f"(hi) : "l"(v));
}
__device__ __forceinline__ unsigned long long pack2(float lo, float hi) {
    unsigned long long v;
    asm("mov.b64 %0, {%1, %2};" : "=l"(v) : "f"(lo), "f"(hi));
    return v;
}
__device__ __forceinline__ unsigned long long dup2(float f) {
    unsigned long long v;
    asm("mov.b64 %0, {%1, %1};" : "=l"(v) : "f"(f));
    return v;
}
__device__ __forceinline__ float tanh_fast(float a) {
    float y; asm("tanh.approx.f32 %0, %1;" : "=f"(y) : "f"(a)); return y;
}
__device__ __forceinline__ float exp_fast(float a) {
    float y; asm("ex2.approx.f32 %0, %1;" : "=f"(y) : "f"(a * 1.442695041f)); return y;
}

// SMEM layout (bytes): [0,131072) Wh+Wl frag tables; XZ; D buffer
#define OFF_XZ_F  32768        // float index; 256 rows x 66
#define XZ_STRIDE 66
#define OFF_D_F   49664        // float index; 256 rows x 18
#define D_STRIDE  18
#define SMEM_BYTES 217088

__global__ __launch_bounds__(THREADS, 1)
void flow_kernel(const float* __restrict__ x,
                 const float* __restrict__ ipar,
                 float* __restrict__ z_out,
                 float* __restrict__ ld_out,
                 int B, int tiles, int has_ld)
{
    extern __shared__ char sm[];
    float* smf = (float*)sm;
    const int tid  = threadIdx.x;
    const int warp = tid >> 5;
    const int lane = tid & 31;
    const int g    = lane >> 2;          // row group
    const int tg   = lane & 3;           // col group
    const int c0   = tg * 2;
    const int r1   = warp * 16 + g;      // rows r1, r1+8 of the tile
    const int es   = tid & 255;          // epilogue sample
    const int eh   = tid >> 8;           // epilogue layer parity within chunk

    // ---- stage fragment weight tables once (128 KB) ----
    {
        const float4* ws = (const float4*)g_Wfrag;
        float4* wd = (float4*)sm;
        #pragma unroll
        for (int k = 0; k < 16; k++) wd[tid + k * 512] = ws[tid + k * 512];
    }
    const unsigned long long* sWh = (const unsigned long long*)sm;
    const unsigned long long* sWl = sWh + 8192;
    float* XZ = smf + OFF_XZ_F;
    float* DB = smf + OFF_D_F;

    const float mu0 = ipar[0];
    const float al0 = ipar[1];
    const float e0  = exp_fast(al0);

    for (int t = blockIdx.x; t < tiles; t += gridDim.x) {
        const int base = t * TILE_M;
        const int validRows = min(TILE_M, B - base);

        // ---- stage x tile (coalesced) ----
        {
            const float2* xg = (const float2*)(x + (size_t)base * 64);
            #pragma unroll
            for (int k = 0; k < 16; k++) {
                int idx = tid + k * 512;          // 0..8191 (256 rows x 32 f2)
                int row = idx >> 5, cc2 = idx & 31;
                if (row < validRows)
                    *(float2*)&XZ[row * XZ_STRIDE + 2 * cc2] = xg[idx];
            }
        }
        __syncthreads();

        // ---- build A fragments (bf16 split) ----
        uint32_t Ah[16], Al[16];
        #pragma unroll
        for (int kt = 0; kt < 4; kt++) {
            int kb = kt * 16;
            float2 p[4];
            p[0] = *(const float2*)&XZ[r1 * XZ_STRIDE + kb + c0];
            p[1] = *(const float2*)&XZ[(r1 + 8) * XZ_STRIDE + kb + c0];
            p[2] = *(const float2*)&XZ[r1 * XZ_STRIDE + kb + c0 + 8];
            p[3] = *(const float2*)&XZ[(r1 + 8) * XZ_STRIDE + kb + c0 + 8];
            #pragma unroll
            for (int j = 0; j < 4; j++) {
                uint32_t hbits = packbf(p[j].x, p[j].y);
                float rx = p[j].x - __uint_as_float(hbits << 16);
                float ry = p[j].y - __uint_as_float(hbits & 0xFFFF0000u);
                Ah[kt * 4 + j] = hbits;
                Al[kt * 4 + j] = packbf(rx, ry);
            }
        }

        float ld_acc = (eh == 0) ? al0 : 0.0f;

        // ---- chunk loop: 2 layers per chunk ----
        #pragma unroll
        for (int c = 0; c < NCHUNK; c++) {
            float da0[4] = {0,0,0,0}, db0[4] = {0,0,0,0};
            float da1[4] = {0,0,0,0}, db1[4] = {0,0,0,0};
            #pragma unroll
            for (int kt = 0; kt < 4; kt++) {
                unsigned long long wh0 = sWh[((2 * c) * 4 + kt) * 32 + lane];
                unsigned long long wl0 = sWl[((2 * c) * 4 + kt) * 32 + lane];
                unsigned long long wh1 = sWh[((2 * c + 1) * 4 + kt) * 32 + lane];
                unsigned long long wl1 = sWl[((2 * c + 1) * 4 + kt) * 32 + lane];
                uint32_t h0b0 = (uint32_t)wh0, h0b1 = (uint32_t)(wh0 >> 32);
                uint32_t l0b0 = (uint32_t)wl0, l0b1 = (uint32_t)(wl0 >> 32);
                uint32_t h1b0 = (uint32_t)wh1, h1b1 = (uint32_t)(wh1 >> 32);
                uint32_t l1b0 = (uint32_t)wl1, l1b1 = (uint32_t)(wl1 >> 32);
                mma_bf16(da0, &Ah[kt * 4], h0b0, h0b1);
                mma_bf16(da1, &Ah[kt * 4], h1b0, h1b1);
                mma_bf16(db0, &Al[kt * 4], h0b0, h0b1);
                mma_bf16(db1, &Al[kt * 4], h1b0, h1b1);
                mma_bf16(db0, &Ah[kt * 4], l0b0, l0b1);
                mma_bf16(db1, &Ah[kt * 4], l1b0, l1b1);
            }
            // store D: rows r1, r1+8; cols j*8 + c0 (+1)
            *(float2*)&DB[r1 * D_STRIDE + c0]            = make_float2(da0[0] + db0[0], da0[1] + db0[1]);
            *(float2*)&DB[(r1 + 8) * D_STRIDE + c0]      = make_float2(da0[2] + db0[2], da0[3] + db0[3]);
            *(float2*)&DB[r1 * D_STRIDE + 8 + c0]        = make_float2(da1[0] + db1[0], da1[1] + db1[1]);
            *(float2*)&DB[(r1 + 8) * D_STRIDE + 8 + c0]  = make_float2(da1[2] + db1[2], da1[3] + db1[3]);
            __syncthreads();

            // ---- epilogue: 2 threads per sample, one layer each ----
            const int l = 2 * c + eh;
            if (l < L_NUM) {
                unsigned long long ma = pack2(c_B2[2 * l], c_B2[2 * l + 1]);
                const float* drow = DB + es * D_STRIDE + eh * 8;
                #pragma unroll
                for (int h = 0; h < 8; h++) {
                    float pre = drow[h] + c_B1[l * 8 + h];
                    float hv = tanh_fast(pre);
                    ma = fma2(dup2(hv), c_W2p[l * 8 + h], ma);
                }
                float mu, al;
                unpack2(ma, mu, al);
                ld_acc += al;
                if (c == 0 && eh == 0)
                    XZ[es * XZ_STRIDE] = XZ[es * XZ_STRIDE] * e0 + mu0;
                float xn = XZ[es * XZ_STRIDE + l + 1];
                XZ[es * XZ_STRIDE + l + 1] = xn * exp_fast(al) + mu;
            }
            __syncthreads();
        }

        // ---- log-det reduce (2 partials per sample) via D buffer ----
        DB[eh * 256 + es] = ld_acc;
        __syncthreads();
        if (has_ld && tid < validRows)
            ld_out[base + tid] = DB[tid] + DB[256 + tid];

        // ---- coalesced z writeback ----
        {
            float2* zg = (float2*)(z_out + (size_t)base * 64);
            #pragma unroll
            for (int k = 0; k < 16; k++) {
                int idx = tid + k * 512;
                int row = idx >> 5, cc2 = idx & 31;
                if (row < validRows)
                    zg[idx] = *(const float2*)&XZ[row * XZ_STRIDE + 2 * cc2];
            }
        }
        __syncthreads();
    }
}

extern "C" void kernel_launch(void* const* d_in, const int* in_sizes, int n_in,
                              void* d_out, int out_size) {
    const float* x  = (const float*)d_in[0];
    const float* ip = (const float*)d_in[1];
    const float* W1 = (const float*)d_in[2];
    const float* b1 = (const float*)d_in[3];
    const float* W2 = (const float*)d_in[4];
    const float* b2 = (const float*)d_in[5];

    int B = in_sizes[0] / 64;
    float* z   = (float*)d_out;
    float* ldp = z + (size_t)B * 64;
    int has_ld = (out_size >= B * 64 + B) ? 1 : 0;
    int tiles = (B + TILE_M - 1) / TILE_M;

    int prep_n = 8192 + 512;
    prep_kernel<<<(prep_n + 255) / 256, 256>>>(W1, W2, b1, b2);

    void* p = nullptr;
    cudaGetSymbolAddress(&p, g_B1);
    cudaMemcpyToSymbolAsync(c_B1, p, sizeof(g_B1), 0, cudaMemcpyDeviceToDevice);
    cudaGetSymbolAddress(&p, g_W2p);
    cudaMemcpyToSymbolAsync(c_W2p, p, sizeof(g_W2p), 0, cudaMemcpyDeviceToDevice);
    cudaGetSymbolAddress(&p, g_B2);
    cudaMemcpyToSymbolAsync(c_B2, p, sizeof(g_B2), 0, cudaMemcpyDeviceToDevice);

    cudaFuncSetAttribute(flow_kernel, cudaFuncAttributeMaxDynamicSharedMemorySize, SMEM_BYTES);
    int grid = tiles < 148 ? tiles : 148;
    flow_kernel<<<grid, THREADS, SMEM_BYTES>>>(x, ip, z, ldp, B, tiles, has_ld);
}

// round 13
// speedup vs baseline: 2.6318x; 1.2780x over previous
#include <cuda_runtime.h>
#include <cuda_bf16.h>
#include <cstdint>

#define L_NUM  63
#define THREADS 512
#define TILE_M  256
#define NCHUNK  32            // 2 layers (n-tiles) per chunk

// triangular fragment-block prefix: blocks before layer l (each layer l has l/16+1 kt-blocks)
__host__ __device__ __forceinline__ constexpr int OffF(int l) {
    int q = l >> 4, r = l & 15;
    int s = 0;
    for (int g = 0; g < q; g++) s += 16 * (g + 1);
    return s + r * (q + 1);
}
#define TOTBLK 156            // OffF(63)

// compact fragment tables: [0, TOTBLK*32) = Wh, [TOTBLK*32, 2*TOTBLK*32) = Wl
// entry = (OffF(l) + kt)*32 + lane ; u64 = {b0 (lo32), b1 (hi32)}
__device__ unsigned long long g_Wfrag[2 * TOTBLK * 32];
__device__ float g_B1[504];
__device__ unsigned long long g_W2p[504];
__device__ float g_B2[126];

__constant__ float c_B1[504];
__constant__ unsigned long long c_W2p[504];
__constant__ float c_B2[126];

__global__ void prep_kernel(const float* __restrict__ W1, const float* __restrict__ W2,
                            const float* __restrict__ b1, const float* __restrict__ b2) {
    int i = blockIdx.x * blockDim.x + threadIdx.x;
    if (i < 8192) {                       // domain: nt(64) x kt(4) x lane(32)
        int lane = i & 31;
        int kt   = (i >> 5) & 3;
        int nt   = i >> 7;
        if (nt >= L_NUM || kt > (nt >> 4)) return;   // triangular skip
        int n  = nt * 8 + (lane >> 2);
        int k0 = kt * 16 + (lane & 3) * 2;
        int l = n >> 3, h = n & 7;
        int ks[4] = { k0, k0 + 1, k0 + 8, k0 + 9 };
        uint32_t bh[4], bl[4];
        #pragma unroll
        for (int j = 0; j < 4; j++) {
            int k = ks[j];
            float v = 0.0f;
            if (k <= l) v = W1[l * 504 + h * 63 + k];
            __nv_bfloat16 vh = __float2bfloat16_rn(v);
            float res = v - __bfloat162float(vh);
            __nv_bfloat16 vl = __float2bfloat16_rn(res);
            bh[j] = (uint32_t)__bfloat16_as_ushort(vh);
            bl[j] = (uint32_t)__bfloat16_as_ushort(vl);
        }
        uint32_t b0h = bh[0] | (bh[1] << 16), b1h = bh[2] | (bh[3] << 16);
        uint32_t b0l = bl[0] | (bl[1] << 16), b1l = bl[2] | (bl[3] << 16);
        int dst = (OffF(nt) + kt) * 32 + lane;
        g_Wfrag[dst]               = (unsigned long long)b0h | ((unsigned long long)b1h << 32);
        g_Wfrag[TOTBLK * 32 + dst] = (unsigned long long)b0l | ((unsigned long long)b1l << 32);
    } else {
        int j = i - 8192;
        if (j < 504) {
            int l = j >> 3, h = j & 7;
            float2 w = make_float2(W2[l * 16 + h], W2[l * 16 + 8 + h]);
            g_W2p[j] = *(unsigned long long*)&w;
            g_B1[j] = b1[j];
            if (j < 126) g_B2[j] = b2[j];
        }
    }
}

// ---------------- helpers ----------------
__device__ __forceinline__ void mma_bf16(float* d, const uint32_t* a, uint32_t b0, uint32_t b1) {
    asm volatile(
        "mma.sync.aligned.m16n8k16.row.col.f32.bf16.bf16.f32 "
        "{%0,%1,%2,%3}, {%4,%5,%6,%7}, {%8,%9}, {%0,%1,%2,%3};"
        : "+f"(d[0]), "+f"(d[1]), "+f"(d[2]), "+f"(d[3])
        : "r"(a[0]), "r"(a[1]), "r"(a[2]), "r"(a[3]), "r"(b0), "r"(b1));
}
__device__ __forceinline__ uint32_t packbf(float lo, float hi) {
    uint32_t r;
    asm("cvt.rn.bf16x2.f32 %0, %1, %2;" : "=r"(r) : "f"(hi), "f"(lo));
    return r;
}
__device__ __forceinline__ unsigned long long fma2(unsigned long long a,
                                                   unsigned long long b,
                                                   unsigned long long c) {
    unsigned long long d;
    asm("fma.rn.f32x2 %0, %1, %2, %3;" : "=l"(d) : "l"(a), "l"(b), "l"(c));
    return d;
}
__device__ __forceinline__ void unpack2(unsigned long long v, float& lo, float& hi) {
    asm("mov.b64 {%0, %1}, %2;" : "=f"(lo), "=f"(hi) : "l"(v));
}
__device__ __forceinline__ unsigned long long pack2(float lo, float hi) {
    unsigned long long v;
    asm("mov.b64 %0, {%1, %2};" : "=l"(v) : "f"(lo), "f"(hi));
    return v;
}
__device__ __forceinline__ unsigned long long dup2(float f) {
    unsigned long long v;
    asm("mov.b64 %0, {%1, %1};" : "=l"(v) : "f"(f));
    return v;
}
__device__ __forceinline__ float tanh_fast(float a) {
    float y; asm("tanh.approx.f32 %0, %1;" : "=f"(y) : "f"(a)); return y;
}
__device__ __forceinline__ float exp_fast(float a) {
    float y; asm("ex2.approx.f32 %0, %1;" : "=f"(y) : "f"(a * 1.442695041f)); return y;
}

// SMEM (floats): [0, 19968) frag tables (79872 B); XZ 256x66; D double buffer 2x256x18
#define OFF_XZ_F  19968
#define XZ_STRIDE 66
#define OFF_D_F   36864
#define D_STRIDE  18
#define D_BUF     (256 * D_STRIDE)
#define SMEM_BYTES 184320

__global__ __launch_bounds__(THREADS, 1)
void flow_kernel(const float* __restrict__ x,
                 const float* __restrict__ ipar,
                 float* __restrict__ z_out,
                 float* __restrict__ ld_out,
                 int B, int tiles, int has_ld)
{
    extern __shared__ char sm[];
    float* smf = (float*)sm;
    const int tid  = threadIdx.x;
    const int warp = tid >> 5;
    const int lane = tid & 31;
    const int g    = lane >> 2;
    const int tg   = lane & 3;
    const int c0   = tg * 2;
    const int r1   = warp * 16 + g;
    const int es   = tid & 255;          // epilogue sample
    const int eh   = tid >> 8;           // epilogue layer parity within chunk

    // ---- stage compact fragment tables once (79872 B = 4992 float4) ----
    {
        const float4* ws = (const float4*)g_Wfrag;
        float4* wd = (float4*)sm;
        for (int i = tid; i < 4992; i += THREADS) wd[i] = ws[i];
    }
    const unsigned long long* sWh = (const unsigned long long*)sm;
    const unsigned long long* sWl = sWh + TOTBLK * 32;
    float* XZ = smf + OFF_XZ_F;
    float* DBase = smf + OFF_D_F;

    const float mu0 = ipar[0];
    const float al0 = ipar[1];
    const float e0  = exp_fast(al0);

    for (int t = blockIdx.x; t < tiles; t += gridDim.x) {
        const int base = t * TILE_M;
        const int validRows = min(TILE_M, B - base);

        // ---- stage x tile (coalesced) ----
        {
            const float2* xg = (const float2*)(x + (size_t)base * 64);
            #pragma unroll
            for (int k = 0; k < 16; k++) {
                int idx = tid + k * 512;
                int row = idx >> 5, cc2 = idx & 31;
                if (row < validRows)
                    *(float2*)&XZ[row * XZ_STRIDE + 2 * cc2] = xg[idx];
            }
        }
        __syncthreads();

        // ---- build A fragments (bf16 split) ----
        uint32_t Ah[16], Al[16];
        #pragma unroll
        for (int kt = 0; kt < 4; kt++) {
            int kb = kt * 16;
            float2 p[4];
            p[0] = *(const float2*)&XZ[r1 * XZ_STRIDE + kb + c0];
            p[1] = *(const float2*)&XZ[(r1 + 8) * XZ_STRIDE + kb + c0];
            p[2] = *(const float2*)&XZ[r1 * XZ_STRIDE + kb + c0 + 8];
            p[3] = *(const float2*)&XZ[(r1 + 8) * XZ_STRIDE + kb + c0 + 8];
            #pragma unroll
            for (int j = 0; j < 4; j++) {
                uint32_t hbits = packbf(p[j].x, p[j].y);
                float rx = p[j].x - __uint_as_float(hbits << 16);
                float ry = p[j].y - __uint_as_float(hbits & 0xFFFF0000u);
                Ah[kt * 4 + j] = hbits;
                Al[kt * 4 + j] = packbf(rx, ry);
            }
        }

        float ld_acc = (eh == 0) ? al0 : 0.0f;

        // ---- chunk loop: 2 layers per chunk, 1 barrier per chunk (double-buffered D) ----
        #pragma unroll
        for (int c = 0; c < NCHUNK; c++) {
            float* DB = DBase + (c & 1) * D_BUF;
            const int l0 = 2 * c, l1 = 2 * c + 1;
            const int ktmax = (l0 >> 4) + 1;          // triangular: kt <= l/16
            const int ofs0 = OffF(l0), ofs1 = (l1 < L_NUM) ? OffF(l1) : OffF(l0);

            float da0[4] = {0,0,0,0}, db0[4] = {0,0,0,0};
            float da1[4] = {0,0,0,0}, db1[4] = {0,0,0,0};
            #pragma unroll
            for (int kt = 0; kt < 4; kt++) {
                if (kt < ktmax) {
                    unsigned long long wh0 = sWh[(ofs0 + kt) * 32 + lane];
                    unsigned long long wl0 = sWl[(ofs0 + kt) * 32 + lane];
                    unsigned long long wh1 = sWh[(ofs1 + kt) * 32 + lane];
                    unsigned long long wl1 = sWl[(ofs1 + kt) * 32 + lane];
                    uint32_t h0b0 = (uint32_t)wh0, h0b1 = (uint32_t)(wh0 >> 32);
                    uint32_t l0b0 = (uint32_t)wl0, l0b1 = (uint32_t)(wl0 >> 32);
                    uint32_t h1b0 = (uint32_t)wh1, h1b1 = (uint32_t)(wh1 >> 32);
                    uint32_t l1b0 = (uint32_t)wl1, l1b1 = (uint32_t)(wl1 >> 32);
                    mma_bf16(da0, &Ah[kt * 4], h0b0, h0b1);
                    mma_bf16(da1, &Ah[kt * 4], h1b0, h1b1);
                    mma_bf16(db0, &Al[kt * 4], h0b0, h0b1);
                    mma_bf16(db1, &Al[kt * 4], h1b0, h1b1);
                    mma_bf16(db0, &Ah[kt * 4], l0b0, l0b1);
                    mma_bf16(db1, &Ah[kt * 4], l1b0, l1b1);
                }
            }
            *(float2*)&DB[r1 * D_STRIDE + c0]            = make_float2(da0[0] + db0[0], da0[1] + db0[1]);
            *(float2*)&DB[(r1 + 8) * D_STRIDE + c0]      = make_float2(da0[2] + db0[2], da0[3] + db0[3]);
            *(float2*)&DB[r1 * D_STRIDE + 8 + c0]        = make_float2(da1[0] + db1[0], da1[1] + db1[1]);
            *(float2*)&DB[(r1 + 8) * D_STRIDE + 8 + c0]  = make_float2(da1[2] + db1[2], da1[3] + db1[3]);
            __syncthreads();

            // ---- epilogue: 2 threads per sample, one layer each ----
            const int l = 2 * c + eh;
            if (l < L_NUM) {
                unsigned long long ma = pack2(c_B2[2 * l], c_B2[2 * l + 1]);
                const float* drow = DB + es * D_STRIDE + eh * 8;
                #pragma unroll
                for (int h = 0; h < 8; h++) {
                    float pre = drow[h] + c_B1[l * 8 + h];
                    float hv = tanh_fast(pre);
                    ma = fma2(dup2(hv), c_W2p[l * 8 + h], ma);
                }
                float mu, al;
                unpack2(ma, mu, al);
                ld_acc += al;
                if (c == 0 && eh == 0)
                    XZ[es * XZ_STRIDE] = XZ[es * XZ_STRIDE] * e0 + mu0;
                float xn = XZ[es * XZ_STRIDE + l + 1];
                XZ[es * XZ_STRIDE + l + 1] = xn * exp_fast(al) + mu;
            }
        }
        __syncthreads();

        // ---- log-det reduce (2 partials per sample) ----
        DBase[eh * 256 + es] = ld_acc;
        __syncthreads();
        if (has_ld && tid < validRows)
            ld_out[base + tid] = DBase[tid] + DBase[256 + tid];

        // ---- coalesced z writeback ----
        {
            float2* zg = (float2*)(z_out + (size_t)base * 64);
            #pragma unroll
            for (int k = 0; k < 16; k++) {
                int idx = tid + k * 512;
                int row = idx >> 5, cc2 = idx & 31;
                if (row < validRows)
                    zg[idx] = *(const float2*)&XZ[row * XZ_STRIDE + 2 * cc2];
            }
        }
        __syncthreads();
    }
}

extern "C" void kernel_launch(void* const* d_in, const int* in_sizes, int n_in,
                              void* d_out, int out_size) {
    const float* x  = (const float*)d_in[0];
    const float* ip = (const float*)d_in[1];
    const float* W1 = (const float*)d_in[2];
    const float* b1 = (const float*)d_in[3];
    const float* W2 = (const float*)d_in[4];
    const float* b2 = (const float*)d_in[5];

    int B = in_sizes[0] / 64;
    float* z   = (float*)d_out;
    float* ldp = z + (size_t)B * 64;
    int has_ld = (out_size >= B * 64 + B) ? 1 : 0;
    int tiles = (B + TILE_M - 1) / TILE_M;

    int prep_n = 8192 + 512;
    prep_kernel<<<(prep_n + 255) / 256, 256>>>(W1, W2, b1, b2);

    void* p = nullptr;
    cudaGetSymbolAddress(&p, g_B1);
    cudaMemcpyToSymbolAsync(c_B1, p, sizeof(g_B1), 0, cudaMemcpyDeviceToDevice);
    cudaGetSymbolAddress(&p, g_W2p);
    cudaMemcpyToSymbolAsync(c_W2p, p, sizeof(g_W2p), 0, cudaMemcpyDeviceToDevice);
    cudaGetSymbolAddress(&p, g_B2);
    cudaMemcpyToSymbolAsync(c_B2, p, sizeof(g_B2), 0, cudaMemcpyDeviceToDevice);

    cudaFuncSetAttribute(flow_kernel, cudaFuncAttributeMaxDynamicSharedMemorySize, SMEM_BYTES);
    int grid = tiles < 148 ? tiles : 148;
    flow_kernel<<<grid, THREADS, SMEM_BYTES>>>(x, ip, z, ldp, B, tiles, has_ld);
}

// round 14
// speedup vs baseline: 2.6433x; 1.0044x over previous
#include <cuda_runtime.h>
#include <cuda_bf16.h>
#include <cstdint>

#define L_NUM  63
#define THREADS 512
#define TILE_M  256
#define NCHUNK  32            // 2 layers (n-tiles) per chunk

// triangular fragment-block prefix: blocks before layer l (each layer l has l/16+1 kt-blocks)
__host__ __device__ __forceinline__ constexpr int OffF(int l) {
    int q = l >> 4, r = l & 15;
    int s = 0;
    for (int g = 0; g < q; g++) s += 16 * (g + 1);
    return s + r * (q + 1);
}
#define TOTBLK 156            // OffF(63)

__device__ unsigned long long g_Wfrag[2 * TOTBLK * 32];
__device__ float g_B1[504];
__device__ unsigned long long g_W2p[504];
__device__ float g_B2[126];

__constant__ float c_B1[504];
__constant__ unsigned long long c_W2p[504];
__constant__ float c_B2[126];

__global__ void prep_kernel(const float* __restrict__ W1, const float* __restrict__ W2,
                            const float* __restrict__ b1, const float* __restrict__ b2) {
    int i = blockIdx.x * blockDim.x + threadIdx.x;
    if (i < 8192) {                       // domain: nt(64) x kt(4) x lane(32)
        int lane = i & 31;
        int kt   = (i >> 5) & 3;
        int nt   = i >> 7;
        if (nt >= L_NUM || kt > (nt >> 4)) return;   // triangular skip
        int n  = nt * 8 + (lane >> 2);
        int k0 = kt * 16 + (lane & 3) * 2;
        int l = n >> 3, h = n & 7;
        int ks[4] = { k0, k0 + 1, k0 + 8, k0 + 9 };
        uint32_t bh[4], bl[4];
        #pragma unroll
        for (int j = 0; j < 4; j++) {
            int k = ks[j];
            float v = 0.0f;
            if (k <= l) v = W1[l * 504 + h * 63 + k];
            __nv_bfloat16 vh = __float2bfloat16_rn(v);
            float res = v - __bfloat162float(vh);
            __nv_bfloat16 vl = __float2bfloat16_rn(res);
            bh[j] = (uint32_t)__bfloat16_as_ushort(vh);
            bl[j] = (uint32_t)__bfloat16_as_ushort(vl);
        }
        uint32_t b0h = bh[0] | (bh[1] << 16), b1h = bh[2] | (bh[3] << 16);
        uint32_t b0l = bl[0] | (bl[1] << 16), b1l = bl[2] | (bl[3] << 16);
        int dst = (OffF(nt) + kt) * 32 + lane;
        g_Wfrag[dst]               = (unsigned long long)b0h | ((unsigned long long)b1h << 32);
        g_Wfrag[TOTBLK * 32 + dst] = (unsigned long long)b0l | ((unsigned long long)b1l << 32);
    } else {
        int j = i - 8192;
        if (j < 504) {
            int l = j >> 3, h = j & 7;
            float2 w = make_float2(W2[l * 16 + h], W2[l * 16 + 8 + h]);
            g_W2p[j] = *(unsigned long long*)&w;
            g_B1[j] = b1[j];
            if (j < 126) g_B2[j] = b2[j];
        }
    }
}

// ---------------- helpers ----------------
__device__ __forceinline__ void mma_bf16(float* d, const uint32_t* a, uint32_t b0, uint32_t b1) {
    asm volatile(
        "mma.sync.aligned.m16n8k16.row.col.f32.bf16.bf16.f32 "
        "{%0,%1,%2,%3}, {%4,%5,%6,%7}, {%8,%9}, {%0,%1,%2,%3};"
        : "+f"(d[0]), "+f"(d[1]), "+f"(d[2]), "+f"(d[3])
        : "r"(a[0]), "r"(a[1]), "r"(a[2]), "r"(a[3]), "r"(b0), "r"(b1));
}
__device__ __forceinline__ uint32_t packbf(float lo, float hi) {
    uint32_t r;
    asm("cvt.rn.bf16x2.f32 %0, %1, %2;" : "=r"(r) : "f"(hi), "f"(lo));
    return r;
}
__device__ __forceinline__ unsigned long long fma2(unsigned long long a,
                                                   unsigned long long b,
                                                   unsigned long long c) {
    unsigned long long d;
    asm("fma.rn.f32x2 %0, %1, %2, %3;" : "=l"(d) : "l"(a), "l"(b), "l"(c));
    return d;
}
__device__ __forceinline__ void unpack2(unsigned long long v, float& lo, float& hi) {
    asm("mov.b64 {%0, %1}, %2;" : "=f"(lo), "=f"(hi) : "l"(v));
}
__device__ __forceinline__ unsigned long long pack2(float lo, float hi) {
    unsigned long long v;
    asm("mov.b64 %0, {%1, %2};" : "=l"(v) : "f"(lo), "f"(hi));
    return v;
}
__device__ __forceinline__ unsigned long long dup2(float f) {
    unsigned long long v;
    asm("mov.b64 %0, {%1, %1};" : "=l"(v) : "f"(f));
    return v;
}
__device__ __forceinline__ float tanh_fast(float a) {
    float y; asm("tanh.approx.f32 %0, %1;" : "=f"(y) : "f"(a)); return y;
}
__device__ __forceinline__ float exp_fast(float a) {
    float y; asm("ex2.approx.f32 %0, %1;" : "=f"(y) : "f"(a * 1.442695041f)); return y;
}

// SMEM (floats): [0, 19968) frag tables (79872 B); XZ 256x66; D double buffer 2x256x18
#define OFF_XZ_F  19968
#define XZ_STRIDE 66
#define OFF_D_F   36864
#define D_STRIDE  18
#define D_BUF     (256 * D_STRIDE)
#define SMEM_BYTES 184320

__global__ __launch_bounds__(THREADS, 1)
void flow_kernel(const float* __restrict__ x,
                 const float* __restrict__ ipar,
                 float* __restrict__ z_out,
                 float* __restrict__ ld_out,
                 int B, int tiles, int has_ld)
{
    extern __shared__ char sm[];
    float* smf = (float*)sm;
    const int tid  = threadIdx.x;
    const int warp = tid >> 5;
    const int lane = tid & 31;
    const int g    = lane >> 2;
    const int tg   = lane & 3;
    const int c0   = tg * 2;
    const int r1   = warp * 16 + g;
    const int es   = tid & 255;          // epilogue sample
    const int eh   = tid >> 8;           // epilogue layer parity within chunk

    // ---- stage compact fragment tables once (79872 B = 4992 float4) ----
    {
        const float4* ws = (const float4*)g_Wfrag;
        float4* wd = (float4*)sm;
        for (int i = tid; i < 4992; i += THREADS) wd[i] = ws[i];
    }
    const unsigned long long* sWh = (const unsigned long long*)sm;
    const unsigned long long* sWl = sWh + TOTBLK * 32;
    float* XZ = smf + OFF_XZ_F;
    float* DBase = smf + OFF_D_F;

    const float mu0 = ipar[0];
    const float al0 = ipar[1];
    const float e0  = exp_fast(al0);

    for (int t = blockIdx.x; t < tiles; t += gridDim.x) {
        const int base = t * TILE_M;
        const int validRows = min(TILE_M, B - base);

        // ---- stage x tile (coalesced) ----
        {
            const float2* xg = (const float2*)(x + (size_t)base * 64);
            #pragma unroll
            for (int k = 0; k < 16; k++) {
                int idx = tid + k * 512;
                int row = idx >> 5, cc2 = idx & 31;
                if (row < validRows)
                    *(float2*)&XZ[row * XZ_STRIDE + 2 * cc2] = xg[idx];
            }
        }
        __syncthreads();

        // ---- build A fragments (bf16 split) ----
        uint32_t Ah[16], Al[16];
        #pragma unroll
        for (int kt = 0; kt < 4; kt++) {
            int kb = kt * 16;
            float2 p[4];
            p[0] = *(const float2*)&XZ[r1 * XZ_STRIDE + kb + c0];
            p[1] = *(const float2*)&XZ[(r1 + 8) * XZ_STRIDE + kb + c0];
            p[2] = *(const float2*)&XZ[r1 * XZ_STRIDE + kb + c0 + 8];
            p[3] = *(const float2*)&XZ[(r1 + 8) * XZ_STRIDE + kb + c0 + 8];
            #pragma unroll
            for (int j = 0; j < 4; j++) {
                uint32_t hbits = packbf(p[j].x, p[j].y);
                float rx = p[j].x - __uint_as_float(hbits << 16);
                float ry = p[j].y - __uint_as_float(hbits & 0xFFFF0000u);
                Ah[kt * 4 + j] = hbits;
                Al[kt * 4 + j] = packbf(rx, ry);
            }
        }

        float ld_acc = (eh == 0) ? al0 : 0.0f;

        // ---- prologue: chunk 0 MMA -> DB[0] ----
        {
            float da0[4] = {0,0,0,0}, db0[4] = {0,0,0,0};
            float da1[4] = {0,0,0,0}, db1[4] = {0,0,0,0};
            {   // layers 0,1: ktmax = 1
                unsigned long long wh0 = sWh[(OffF(0)) * 32 + lane];
                unsigned long long wl0 = sWl[(OffF(0)) * 32 + lane];
                unsigned long long wh1 = sWh[(OffF(1)) * 32 + lane];
                unsigned long long wl1 = sWl[(OffF(1)) * 32 + lane];
                mma_bf16(da0, &Ah[0], (uint32_t)wh0, (uint32_t)(wh0 >> 32));
                mma_bf16(da1, &Ah[0], (uint32_t)wh1, (uint32_t)(wh1 >> 32));
                mma_bf16(db0, &Al[0], (uint32_t)wh0, (uint32_t)(wh0 >> 32));
                mma_bf16(db1, &Al[0], (uint32_t)wh1, (uint32_t)(wh1 >> 32));
                mma_bf16(db0, &Ah[0], (uint32_t)wl0, (uint32_t)(wl0 >> 32));
                mma_bf16(db1, &Ah[0], (uint32_t)wl1, (uint32_t)(wl1 >> 32));
            }
            float* DB = DBase;
            *(float2*)&DB[r1 * D_STRIDE + c0]            = make_float2(da0[0] + db0[0], da0[1] + db0[1]);
            *(float2*)&DB[(r1 + 8) * D_STRIDE + c0]      = make_float2(da0[2] + db0[2], da0[3] + db0[3]);
            *(float2*)&DB[r1 * D_STRIDE + 8 + c0]        = make_float2(da1[0] + db1[0], da1[1] + db1[1]);
            *(float2*)&DB[(r1 + 8) * D_STRIDE + 8 + c0]  = make_float2(da1[2] + db1[2], da1[3] + db1[3]);
        }
        __syncthreads();

        // ---- pipelined chunk loop: issue MMA(c+1), overlap epilogue(c), store D(c+1) ----
        #pragma unroll
        for (int c = 0; c < NCHUNK; c++) {
            float da0[4] = {0,0,0,0}, db0[4] = {0,0,0,0};
            float da1[4] = {0,0,0,0}, db1[4] = {0,0,0,0};
            if (c + 1 < NCHUNK) {
                const int l0 = 2 * (c + 1), l1 = l0 + 1;
                const int ktmax = (l0 >> 4) + 1;
                const int ofs0 = OffF(l0), ofs1 = OffF(l1);
                #pragma unroll
                for (int kt = 0; kt < 4; kt++) {
                    if (kt < ktmax) {
                        unsigned long long wh0 = sWh[(ofs0 + kt) * 32 + lane];
                        unsigned long long wl0 = sWl[(ofs0 + kt) * 32 + lane];
                        unsigned long long wh1 = sWh[(ofs1 + kt) * 32 + lane];
                        unsigned long long wl1 = sWl[(ofs1 + kt) * 32 + lane];
                        mma_bf16(da0, &Ah[kt * 4], (uint32_t)wh0, (uint32_t)(wh0 >> 32));
                        mma_bf16(da1, &Ah[kt * 4], (uint32_t)wh1, (uint32_t)(wh1 >> 32));
                        mma_bf16(db0, &Al[kt * 4], (uint32_t)wh0, (uint32_t)(wh0 >> 32));
                        mma_bf16(db1, &Al[kt * 4], (uint32_t)wh1, (uint32_t)(wh1 >> 32));
                        mma_bf16(db0, &Ah[kt * 4], (uint32_t)wl0, (uint32_t)(wl0 >> 32));
                        mma_bf16(db1, &Ah[kt * 4], (uint32_t)wl1, (uint32_t)(wl1 >> 32));
                    }
                }
            }

            // ---- epilogue(c): overlaps the in-flight MMAs above ----
            {
                const float* DB = DBase + (c & 1) * D_BUF;
                const int l = 2 * c + eh;
                if (l < L_NUM) {
                    unsigned long long ma = pack2(c_B2[2 * l], c_B2[2 * l + 1]);
                    const float* drow = DB + es * D_STRIDE + eh * 8;
                    #pragma unroll
                    for (int h = 0; h < 8; h++) {
                        float pre = drow[h] + c_B1[l * 8 + h];
                        float hv = tanh_fast(pre);
                        ma = fma2(dup2(hv), c_W2p[l * 8 + h], ma);
                    }
                    float mu, al;
                    unpack2(ma, mu, al);
                    ld_acc += al;
                    if (c == 0 && eh == 0)
                        XZ[es * XZ_STRIDE] = XZ[es * XZ_STRIDE] * e0 + mu0;
                    float xn = XZ[es * XZ_STRIDE + l + 1];
                    XZ[es * XZ_STRIDE + l + 1] = xn * exp_fast(al) + mu;
                }
            }

            // ---- store D(c+1) (accumulators ready by now) ----
            if (c + 1 < NCHUNK) {
                float* DB = DBase + ((c + 1) & 1) * D_BUF;
                *(float2*)&DB[r1 * D_STRIDE + c0]            = make_float2(da0[0] + db0[0], da0[1] + db0[1]);
                *(float2*)&DB[(r1 + 8) * D_STRIDE + c0]      = make_float2(da0[2] + db0[2], da0[3] + db0[3]);
                *(float2*)&DB[r1 * D_STRIDE + 8 + c0]        = make_float2(da1[0] + db1[0], da1[1] + db1[1]);
                *(float2*)&DB[(r1 + 8) * D_STRIDE + 8 + c0]  = make_float2(da1[2] + db1[2], da1[3] + db1[3]);
            }
            __syncthreads();
        }

        // ---- log-det reduce (2 partials per sample) ----
        DBase[eh * 256 + es] = ld_acc;
        __syncthreads();
        if (has_ld && tid < validRows)
            ld_out[base + tid] = DBase[tid] + DBase[256 + tid];

        // ---- coalesced z writeback ----
        {
            float2* zg = (float2*)(z_out + (size_t)base * 64);
            #pragma unroll
            for (int k = 0; k < 16; k++) {
                int idx = tid + k * 512;
                int row = idx >> 5, cc2 = idx & 31;
                if (row < validRows)
                    zg[idx] = *(const float2*)&XZ[row * XZ_STRIDE + 2 * cc2];
            }
        }
        __syncthreads();
    }
}

extern "C" void kernel_launch(void* const* d_in, const int* in_sizes, int n_in,
                              void* d_out, int out_size) {
    const float* x  = (const float*)d_in[0];
    const float* ip = (const float*)d_in[1];
    const float* W1 = (const float*)d_in[2];
    const float* b1 = (const float*)d_in[3];
    const float* W2 = (const float*)d_in[4];
    const float* b2 = (const float*)d_in[5];

    int B = in_sizes[0] / 64;
    float* z   = (float*)d_out;
    float* ldp = z + (size_t)B * 64;
    int has_ld = (out_size >= B * 64 + B) ? 1 : 0;
    int tiles = (B + TILE_M - 1) / TILE_M;

    int prep_n = 8192 + 512;
    prep_kernel<<<(prep_n + 255) / 256, 256>>>(W1, W2, b1, b2);

    void* p = nullptr;
    cudaGetSymbolAddress(&p, g_B1);
    cudaMemcpyToSymbolAsync(c_B1, p, sizeof(g_B1), 0, cudaMemcpyDeviceToDevice);
    cudaGetSymbolAddress(&p, g_W2p);
    cudaMemcpyToSymbolAsync(c_W2p, p, sizeof(g_W2p), 0, cudaMemcpyDeviceToDevice);
    cudaGetSymbolAddress(&p, g_B2);
    cudaMemcpyToSymbolAsync(c_B2, p, sizeof(g_B2), 0, cudaMemcpyDeviceToDevice);

    cudaFuncSetAttribute(flow_kernel, cudaFuncAttributeMaxDynamicSharedMemorySize, SMEM_BYTES);
    int grid = tiles < 148 ? tiles : 148;
    flow_kernel<<<grid, THREADS, SMEM_BYTES>>>(x, ip, z, ldp, B, tiles, has_ld);
}

// round 15
// speedup vs baseline: 2.8585x; 1.0814x over previous
#include <cuda_runtime.h>
#include <cuda_bf16.h>
#include <cstdint>

#define L_NUM  63
#define THREADS 512
#define TILE_M  256
#define NCHUNK  32            // 2 layers (n-tiles) per chunk

// triangular fragment-block prefix: blocks before layer l (each layer l has l/16+1 kt-blocks)
__host__ __device__ __forceinline__ constexpr int OffF(int l) {
    int q = l >> 4, r = l & 15;
    int s = 0;
    for (int g = 0; g < q; g++) s += 16 * (g + 1);
    return s + r * (q + 1);
}
#define TOTBLK 156            // OffF(63)

__device__ unsigned long long g_Wfrag[2 * TOTBLK * 32];
__device__ float g_B1[504];
__device__ unsigned long long g_W2p[504];
__device__ float g_B2[126];

__constant__ float c_B1[504];
__constant__ unsigned long long c_W2p[504];
__constant__ float c_B2[126];

__global__ void prep_kernel(const float* __restrict__ W1, const float* __restrict__ W2,
                            const float* __restrict__ b1, const float* __restrict__ b2) {
    int i = blockIdx.x * blockDim.x + threadIdx.x;
    if (i < 8192) {                       // domain: nt(64) x kt(4) x lane(32)
        int lane = i & 31;
        int kt   = (i >> 5) & 3;
        int nt   = i >> 7;
        if (nt >= L_NUM || kt > (nt >> 4)) return;   // triangular skip
        int n  = nt * 8 + (lane >> 2);
        int k0 = kt * 16 + (lane & 3) * 2;
        int l = n >> 3, h = n & 7;
        int ks[4] = { k0, k0 + 1, k0 + 8, k0 + 9 };
        uint32_t bh[4], bl[4];
        #pragma unroll
        for (int j = 0; j < 4; j++) {
            int k = ks[j];
            float v = 0.0f;
            if (k <= l) v = W1[l * 504 + h * 63 + k];
            __nv_bfloat16 vh = __float2bfloat16_rn(v);
            float res = v - __bfloat162float(vh);
            __nv_bfloat16 vl = __float2bfloat16_rn(res);
            bh[j] = (uint32_t)__bfloat16_as_ushort(vh);
            bl[j] = (uint32_t)__bfloat16_as_ushort(vl);
        }
        uint32_t b0h = bh[0] | (bh[1] << 16), b1h = bh[2] | (bh[3] << 16);
        uint32_t b0l = bl[0] | (bl[1] << 16), b1l = bl[2] | (bl[3] << 16);
        int dst = (OffF(nt) + kt) * 32 + lane;
        g_Wfrag[dst]               = (unsigned long long)b0h | ((unsigned long long)b1h << 32);
        g_Wfrag[TOTBLK * 32 + dst] = (unsigned long long)b0l | ((unsigned long long)b1l << 32);
    } else {
        int j = i - 8192;
        if (j < 504) {
            int l = j >> 3, h = j & 7;
            float2 w = make_float2(W2[l * 16 + h], W2[l * 16 + 8 + h]);
            g_W2p[j] = *(unsigned long long*)&w;
            g_B1[j] = b1[j];
            if (j < 126) g_B2[j] = b2[j];
        }
    }
}

// ---------------- helpers ----------------
__device__ __forceinline__ void mma_bf16(float* d, const uint32_t* a, uint32_t b0, uint32_t b1) {
    asm volatile(
        "mma.sync.aligned.m16n8k16.row.col.f32.bf16.bf16.f32 "
        "{%0,%1,%2,%3}, {%4,%5,%6,%7}, {%8,%9}, {%0,%1,%2,%3};"
        : "+f"(d[0]), "+f"(d[1]), "+f"(d[2]), "+f"(d[3])
        : "r"(a[0]), "r"(a[1]), "r"(a[2]), "r"(a[3]), "r"(b0), "r"(b1));
}
__device__ __forceinline__ uint32_t packbf(float lo, float hi) {
    uint32_t r;
    asm("cvt.rn.bf16x2.f32 %0, %1, %2;" : "=r"(r) : "f"(hi), "f"(lo));
    return r;
}
__device__ __forceinline__ unsigned long long fma2(unsigned long long a,
                                                   unsigned long long b,
                                                   unsigned long long c) {
    unsigned long long d;
    asm("fma.rn.f32x2 %0, %1, %2, %3;" : "=l"(d) : "l"(a), "l"(b), "l"(c));
    return d;
}
__device__ __forceinline__ void unpack2(unsigned long long v, float& lo, float& hi) {
    asm("mov.b64 {%0, %1}, %2;" : "=f"(lo), "=f"(hi) : "l"(v));
}
__device__ __forceinline__ unsigned long long pack2(float lo, float hi) {
    unsigned long long v;
    asm("mov.b64 %0, {%1, %2};" : "=l"(v) : "f"(lo), "f"(hi));
    return v;
}
__device__ __forceinline__ unsigned long long dup2(float f) {
    unsigned long long v;
    asm("mov.b64 %0, {%1, %1};" : "=l"(v) : "f"(f));
    return v;
}
__device__ __forceinline__ float tanh_fast(float a) {
    float y; asm("tanh.approx.f32 %0, %1;" : "=f"(y) : "f"(a)); return y;
}
__device__ __forceinline__ float exp_fast(float a) {
    float y; asm("ex2.approx.f32 %0, %1;" : "=f"(y) : "f"(a * 1.442695041f)); return y;
}

// SMEM (floats): [0, 19968) frag tables; XZ 256x66; D single buffer 256x18
#define OFF_XZ_F  19968
#define XZ_STRIDE 66
#define OFF_D_F   36864
#define D_STRIDE  18
#define SMEM_BYTES 165888

__global__ __launch_bounds__(THREADS, 1)
void flow_kernel(const float* __restrict__ x,
                 const float* __restrict__ ipar,
                 float* __restrict__ z_out,
                 float* __restrict__ ld_out,
                 int B, int tiles, int has_ld)
{
    extern __shared__ char sm[];
    float* smf = (float*)sm;
    const int tid  = threadIdx.x;
    const int warp = tid >> 5;
    const int lane = tid & 31;
    const int g    = lane >> 2;
    const int tg   = lane & 3;
    const int c0   = tg * 2;
    const int r1   = warp * 16 + g;
    // warp-local epilogue assignment: lane = (row 0..15 of this warp, layer parity)
    const int erow   = warp * 16 + (lane & 15);
    const int parity = lane >> 4;

    // ---- stage compact fragment tables once ----
    {
        const float4* ws = (const float4*)g_Wfrag;
        float4* wd = (float4*)sm;
        for (int i = tid; i < 4992; i += THREADS) wd[i] = ws[i];
    }
    const unsigned long long* sWh = (const unsigned long long*)sm;
    const unsigned long long* sWl = sWh + TOTBLK * 32;
    float* XZ = smf + OFF_XZ_F;
    float* DB = smf + OFF_D_F;

    const float mu0 = ipar[0];
    const float al0 = ipar[1];
    const float e0  = exp_fast(al0);

    for (int t = blockIdx.x; t < tiles; t += gridDim.x) {
        const int base = t * TILE_M;
        const int validRows = min(TILE_M, B - base);

        // ---- stage x tile (coalesced) ----
        {
            const float2* xg = (const float2*)(x + (size_t)base * 64);
            #pragma unroll
            for (int k = 0; k < 16; k++) {
                int idx = tid + k * 512;
                int row = idx >> 5, cc2 = idx & 31;
                if (row < validRows)
                    *(float2*)&XZ[row * XZ_STRIDE + 2 * cc2] = xg[idx];
            }
        }
        __syncthreads();

        // ---- build A fragments (bf16 split) ----
        uint32_t Ah[16], Al[16];
        #pragma unroll
        for (int kt = 0; kt < 4; kt++) {
            int kb = kt * 16;
            float2 p[4];
            p[0] = *(const float2*)&XZ[r1 * XZ_STRIDE + kb + c0];
            p[1] = *(const float2*)&XZ[(r1 + 8) * XZ_STRIDE + kb + c0];
            p[2] = *(const float2*)&XZ[r1 * XZ_STRIDE + kb + c0 + 8];
            p[3] = *(const float2*)&XZ[(r1 + 8) * XZ_STRIDE + kb + c0 + 8];
            #pragma unroll
            for (int j = 0; j < 4; j++) {
                uint32_t hbits = packbf(p[j].x, p[j].y);
                float rx = p[j].x - __uint_as_float(hbits << 16);
                float ry = p[j].y - __uint_as_float(hbits & 0xFFFF0000u);
                Ah[kt * 4 + j] = hbits;
                Al[kt * 4 + j] = packbf(rx, ry);
            }
        }

        float ld_acc = (parity == 0) ? al0 : 0.0f;
        float* XZrow = XZ + erow * XZ_STRIDE;
        const float* Drow = DB + erow * D_STRIDE + parity * 8;

        // ---- prologue: chunk 0 MMA -> DB (warp-private rows) ----
        {
            float da0[4] = {0,0,0,0}, db0[4] = {0,0,0,0};
            float da1[4] = {0,0,0,0}, db1[4] = {0,0,0,0};
            unsigned long long wh0 = sWh[(OffF(0)) * 32 + lane];
            unsigned long long wl0 = sWl[(OffF(0)) * 32 + lane];
            unsigned long long wh1 = sWh[(OffF(1)) * 32 + lane];
            unsigned long long wl1 = sWl[(OffF(1)) * 32 + lane];
            mma_bf16(da0, &Ah[0], (uint32_t)wh0, (uint32_t)(wh0 >> 32));
            mma_bf16(da1, &Ah[0], (uint32_t)wh1, (uint32_t)(wh1 >> 32));
            mma_bf16(db0, &Al[0], (uint32_t)wh0, (uint32_t)(wh0 >> 32));
            mma_bf16(db1, &Al[0], (uint32_t)wh1, (uint32_t)(wh1 >> 32));
            mma_bf16(db0, &Ah[0], (uint32_t)wl0, (uint32_t)(wl0 >> 32));
            mma_bf16(db1, &Ah[0], (uint32_t)wl1, (uint32_t)(wl1 >> 32));
            *(float2*)&DB[r1 * D_STRIDE + c0]            = make_float2(da0[0] + db0[0], da0[1] + db0[1]);
            *(float2*)&DB[(r1 + 8) * D_STRIDE + c0]      = make_float2(da0[2] + db0[2], da0[3] + db0[3]);
            *(float2*)&DB[r1 * D_STRIDE + 8 + c0]        = make_float2(da1[0] + db1[0], da1[1] + db1[1]);
            *(float2*)&DB[(r1 + 8) * D_STRIDE + 8 + c0]  = make_float2(da1[2] + db1[2], da1[3] + db1[3]);
        }
        __syncwarp();

        // ---- barrier-free pipelined chunk loop (warp-private) ----
        #pragma unroll
        for (int c = 0; c < NCHUNK; c++) {
            float da0[4] = {0,0,0,0}, db0[4] = {0,0,0,0};
            float da1[4] = {0,0,0,0}, db1[4] = {0,0,0,0};
            if (c + 1 < NCHUNK) {
                const int l0 = 2 * (c + 1), l1 = l0 + 1;
                const int ktmax = (l0 >> 4) + 1;
                const int ofs0 = OffF(l0), ofs1 = OffF(l1);
                #pragma unroll
                for (int kt = 0; kt < 4; kt++) {
                    if (kt < ktmax) {
                        unsigned long long wh0 = sWh[(ofs0 + kt) * 32 + lane];
                        unsigned long long wl0 = sWl[(ofs0 + kt) * 32 + lane];
                        unsigned long long wh1 = sWh[(ofs1 + kt) * 32 + lane];
                        unsigned long long wl1 = sWl[(ofs1 + kt) * 32 + lane];
                        mma_bf16(da0, &Ah[kt * 4], (uint32_t)wh0, (uint32_t)(wh0 >> 32));
                        mma_bf16(da1, &Ah[kt * 4], (uint32_t)wh1, (uint32_t)(wh1 >> 32));
                        mma_bf16(db0, &Al[kt * 4], (uint32_t)wh0, (uint32_t)(wh0 >> 32));
                        mma_bf16(db1, &Al[kt * 4], (uint32_t)wh1, (uint32_t)(wh1 >> 32));
                        mma_bf16(db0, &Ah[kt * 4], (uint32_t)wl0, (uint32_t)(wl0 >> 32));
                        mma_bf16(db1, &Ah[kt * 4], (uint32_t)wl1, (uint32_t)(wl1 >> 32));
                    }
                }
            }

            // ---- epilogue(c): warp-local, overlaps the in-flight MMAs ----
            {
                const int l = 2 * c + parity;
                if (l < L_NUM) {
                    unsigned long long ma = pack2(c_B2[2 * l], c_B2[2 * l + 1]);
                    #pragma unroll
                    for (int h = 0; h < 8; h++) {
                        float pre = Drow[h] + c_B1[l * 8 + h];
                        float hv = tanh_fast(pre);
                        ma = fma2(dup2(hv), c_W2p[l * 8 + h], ma);
                    }
                    float mu, al;
                    unpack2(ma, mu, al);
                    ld_acc += al;
                    if (c == 0 && parity == 0)
                        XZrow[0] = XZrow[0] * e0 + mu0;
                    float xn = XZrow[l + 1];
                    XZrow[l + 1] = xn * exp_fast(al) + mu;
                }
            }

            // ---- store D(c+1) into the (now fully consumed) buffer ----
            if (c + 1 < NCHUNK) {
                *(float2*)&DB[r1 * D_STRIDE + c0]            = make_float2(da0[0] + db0[0], da0[1] + db0[1]);
                *(float2*)&DB[(r1 + 8) * D_STRIDE + c0]      = make_float2(da0[2] + db0[2], da0[3] + db0[3]);
                *(float2*)&DB[r1 * D_STRIDE + 8 + c0]        = make_float2(da1[0] + db1[0], da1[1] + db1[1]);
                *(float2*)&DB[(r1 + 8) * D_STRIDE + 8 + c0]  = make_float2(da1[2] + db1[2], da1[3] + db1[3]);
            }
            __syncwarp();
        }

        // ---- log-det: combine the two parity partials via shuffle ----
        {
            float other = __shfl_xor_sync(0xFFFFFFFFu, ld_acc, 16);
            if (has_ld && parity == 0 && erow < validRows)
                ld_out[base + erow] = ld_acc + other;
        }

        __syncthreads();
        // ---- coalesced z writeback ----
        {
            float2* zg = (float2*)(z_out + (size_t)base * 64);
            #pragma unroll
            for (int k = 0; k < 16; k++) {
                int idx = tid + k * 512;
                int row = idx >> 5, cc2 = idx & 31;
                if (row < validRows)
                    zg[idx] = *(const float2*)&XZ[row * XZ_STRIDE + 2 * cc2];
            }
        }
        __syncthreads();
    }
}

extern "C" void kernel_launch(void* const* d_in, const int* in_sizes, int n_in,
                              void* d_out, int out_size) {
    const float* x  = (const float*)d_in[0];
    const float* ip = (const float*)d_in[1];
    const float* W1 = (const float*)d_in[2];
    const float* b1 = (const float*)d_in[3];
    const float* W2 = (const float*)d_in[4];
    const float* b2 = (const float*)d_in[5];

    int B = in_sizes[0] / 64;
    float* z   = (float*)d_out;
    float* ldp = z + (size_t)B * 64;
    int has_ld = (out_size >= B * 64 + B) ? 1 : 0;
    int tiles = (B + TILE_M - 1) / TILE_M;

    int prep_n = 8192 + 512;
    prep_kernel<<<(prep_n + 255) / 256, 256>>>(W1, W2, b1, b2);

    void* p = nullptr;
    cudaGetSymbolAddress(&p, g_B1);
    cudaMemcpyToSymbolAsync(c_B1, p, sizeof(g_B1), 0, cudaMemcpyDeviceToDevice);
    cudaGetSymbolAddress(&p, g_W2p);
    cudaMemcpyToSymbolAsync(c_W2p, p, sizeof(g_W2p), 0, cudaMemcpyDeviceToDevice);
    cudaGetSymbolAddress(&p, g_B2);
    cudaMemcpyToSymbolAsync(c_B2, p, sizeof(g_B2), 0, cudaMemcpyDeviceToDevice);

    cudaFuncSetAttribute(flow_kernel, cudaFuncAttributeMaxDynamicSharedMemorySize, SMEM_BYTES);
    int grid = tiles < 148 ? tiles : 148;
    flow_kernel<<<grid, THREADS, SMEM_BYTES>>>(x, ip, z, ldp, B, tiles, has_ld);
}

// round 16
// speedup vs baseline: 3.1476x; 1.1012x over previous
#include <cuda_runtime.h>
#include <cuda_bf16.h>
#include <cstdint>

#define L_NUM  63
#define THREADS 448
#define TILE_M  448
#define NCHUNK  32            // 2 layers (n-tiles) per chunk

// triangular fragment-block prefix: blocks before layer l (layer l has l/16+1 kt-blocks)
__host__ __device__ __forceinline__ constexpr int OffF(int l) {
    int q = l >> 4, r = l & 15;
    int s = 0;
    for (int g = 0; g < q; g++) s += 16 * (g + 1);
    return s + r * (q + 1);
}
#define TOTBLK 156            // OffF(63)

__device__ unsigned long long g_Wfrag[2 * TOTBLK * 32];
__device__ float g_B1[504];
__device__ unsigned long long g_W2p[504];
__device__ float g_B2[126];

__constant__ float c_B1[504];
__constant__ unsigned long long c_W2p[504];
__constant__ float c_B2[126];

__global__ void prep_kernel(const float* __restrict__ W1, const float* __restrict__ W2,
                            const float* __restrict__ b1, const float* __restrict__ b2) {
    int i = blockIdx.x * blockDim.x + threadIdx.x;
    if (i < 8192) {                       // domain: nt(64) x kt(4) x lane(32)
        int lane = i & 31;
        int kt   = (i >> 5) & 3;
        int nt   = i >> 7;
        if (nt >= L_NUM || kt > (nt >> 4)) return;   // triangular skip
        int n  = nt * 8 + (lane >> 2);
        int k0 = kt * 16 + (lane & 3) * 2;
        int l = n >> 3, h = n & 7;
        int ks[4] = { k0, k0 + 1, k0 + 8, k0 + 9 };
        uint32_t bh[4], bl[4];
        #pragma unroll
        for (int j = 0; j < 4; j++) {
            int k = ks[j];
            float v = 0.0f;
            if (k <= l) v = W1[l * 504 + h * 63 + k];
            __nv_bfloat16 vh = __float2bfloat16_rn(v);
            float res = v - __bfloat162float(vh);
            __nv_bfloat16 vl = __float2bfloat16_rn(res);
            bh[j] = (uint32_t)__bfloat16_as_ushort(vh);
            bl[j] = (uint32_t)__bfloat16_as_ushort(vl);
        }
        uint32_t b0h = bh[0] | (bh[1] << 16), b1h = bh[2] | (bh[3] << 16);
        uint32_t b0l = bl[0] | (bl[1] << 16), b1l = bl[2] | (bl[3] << 16);
        int dst = (OffF(nt) + kt) * 32 + lane;
        g_Wfrag[dst]               = (unsigned long long)b0h | ((unsigned long long)b1h << 32);
        g_Wfrag[TOTBLK * 32 + dst] = (unsigned long long)b0l | ((unsigned long long)b1l << 32);
    } else {
        int j = i - 8192;
        if (j < 504) {
            int l = j >> 3, h = j & 7;
            float2 w = make_float2(W2[l * 16 + h], W2[l * 16 + 8 + h]);
            g_W2p[j] = *(unsigned long long*)&w;
            g_B1[j] = b1[j];
            if (j < 126) g_B2[j] = b2[j];
        }
    }
}

// ---------------- helpers ----------------
__device__ __forceinline__ void mma_bf16(float* d, const uint32_t* a, uint32_t b0, uint32_t b1) {
    asm volatile(
        "mma.sync.aligned.m16n8k16.row.col.f32.bf16.bf16.f32 "
        "{%0,%1,%2,%3}, {%4,%5,%6,%7}, {%8,%9}, {%0,%1,%2,%3};"
        : "+f"(d[0]), "+f"(d[1]), "+f"(d[2]), "+f"(d[3])
        : "r"(a[0]), "r"(a[1]), "r"(a[2]), "r"(a[3]), "r"(b0), "r"(b1));
}
__device__ __forceinline__ uint32_t packbf(float lo, float hi) {
    uint32_t r;
    asm("cvt.rn.bf16x2.f32 %0, %1, %2;" : "=r"(r) : "f"(hi), "f"(lo));
    return r;
}
__device__ __forceinline__ unsigned long long fma2(unsigned long long a,
                                                   unsigned long long b,
                                                   unsigned long long c) {
    unsigned long long d;
    asm("fma.rn.f32x2 %0, %1, %2, %3;" : "=l"(d) : "l"(a), "l"(b), "l"(c));
    return d;
}
__device__ __forceinline__ void unpack2(unsigned long long v, float& lo, float& hi) {
    asm("mov.b64 {%0, %1}, %2;" : "=f"(lo), "=f"(hi) : "l"(v));
}
__device__ __forceinline__ unsigned long long pack2(float lo, float hi) {
    unsigned long long v;
    asm("mov.b64 %0, {%1, %2};" : "=l"(v) : "f"(lo), "f"(hi));
    return v;
}
__device__ __forceinline__ unsigned long long dup2(float f) {
    unsigned long long v;
    asm("mov.b64 %0, {%1, %1};" : "=l"(v) : "f"(f));
    return v;
}
__device__ __forceinline__ float tanh_fast(float a) {
    float y; asm("tanh.approx.f32 %0, %1;" : "=f"(y) : "f"(a)); return y;
}
__device__ __forceinline__ float exp_fast(float a) {
    float y; asm("ex2.approx.f32 %0, %1;" : "=f"(y) : "f"(a * 1.442695041f)); return y;
}

// SMEM (floats): [0, 19968) frag tables; XZ 448x66; D 448x18
#define OFF_XZ_F  19968
#define XZ_STRIDE 66
#define OFF_D_F   49536
#define D_STRIDE  18
#define SMEM_BYTES 230400

__global__ __launch_bounds__(THREADS, 1)
void flow_kernel(const float* __restrict__ x,
                 const float* __restrict__ ipar,
                 float* __restrict__ z_out,
                 float* __restrict__ ld_out,
                 int B, int tiles, int has_ld)
{
    extern __shared__ char sm[];
    float* smf = (float*)sm;
    const int tid  = threadIdx.x;
    const int warp = tid >> 5;
    const int lane = tid & 31;
    const int g    = lane >> 2;
    const int tg   = lane & 3;
    const int c0   = tg * 2;
    const int rb   = warp * 32;          // this warp's 32 rows
    const int r1a  = rb + g;             // rowset0: rows r1a, r1a+8
    const int r1b  = rb + 16 + g;        // rowset1
    const int er0  = rb + (lane & 15);   // epilogue rows (one per rowset)
    const int er1  = er0 + 16;
    const int parity = lane >> 4;        // layer parity within chunk

    // ---- stage compact fragment tables once ----
    {
        const float4* ws = (const float4*)g_Wfrag;
        float4* wd = (float4*)sm;
        for (int i = tid; i < 4992; i += THREADS) wd[i] = ws[i];
    }
    const unsigned long long* sWh = (const unsigned long long*)sm;
    const unsigned long long* sWl = sWh + TOTBLK * 32;
    float* XZ = smf + OFF_XZ_F;
    float* DB = smf + OFF_D_F;

    const float mu0 = ipar[0];
    const float al0 = ipar[1];
    const float e0  = exp_fast(al0);

    for (int t = blockIdx.x; t < tiles; t += gridDim.x) {
        const int base = t * TILE_M;
        const int validRows = min(TILE_M, B - base);

        // ---- stage x tile (coalesced) ----
        {
            const float2* xg = (const float2*)(x + (size_t)base * 64);
            #pragma unroll
            for (int k = 0; k < 32; k++) {
                int idx = tid + k * THREADS;       // 0 .. 448*32-1
                int row = idx >> 5, cc2 = idx & 31;
                if (row < validRows)
                    *(float2*)&XZ[row * XZ_STRIDE + 2 * cc2] = xg[idx];
            }
        }
        __syncthreads();

        // ---- build A fragments for both rowsets (bf16 split) ----
        uint32_t Ah0[16], Al0[16], Ah1[16], Al1[16];
        #pragma unroll
        for (int rs = 0; rs < 2; rs++) {
            const int r1 = rb + rs * 16 + g;
            uint32_t* Ah = rs ? Ah1 : Ah0;
            uint32_t* Al = rs ? Al1 : Al0;
            #pragma unroll
            for (int kt = 0; kt < 4; kt++) {
                int kb = kt * 16;
                float2 p[4];
                p[0] = *(const float2*)&XZ[r1 * XZ_STRIDE + kb + c0];
                p[1] = *(const float2*)&XZ[(r1 + 8) * XZ_STRIDE + kb + c0];
                p[2] = *(const float2*)&XZ[r1 * XZ_STRIDE + kb + c0 + 8];
                p[3] = *(const float2*)&XZ[(r1 + 8) * XZ_STRIDE + kb + c0 + 8];
                #pragma unroll
                for (int j = 0; j < 4; j++) {
                    uint32_t hbits = packbf(p[j].x, p[j].y);
                    float rx = p[j].x - __uint_as_float(hbits << 16);
                    float ry = p[j].y - __uint_as_float(hbits & 0xFFFF0000u);
                    Ah[kt * 4 + j] = hbits;
                    Al[kt * 4 + j] = packbf(rx, ry);
                }
            }
        }

        float ld_0 = (parity == 0) ? al0 : 0.0f;
        float ld_1 = (parity == 0) ? al0 : 0.0f;
        float* XZr0 = XZ + er0 * XZ_STRIDE;
        float* XZr1 = XZ + er1 * XZ_STRIDE;
        const float* Dr0 = DB + er0 * D_STRIDE + parity * 8;
        const float* Dr1 = DB + er1 * D_STRIDE + parity * 8;

        // ---- chunk loop: 2 layers per chunk, warp-private, no block barriers ----
        #pragma unroll
        for (int c = 0; c < NCHUNK; c++) {
            const int l0 = 2 * c, l1 = 2 * c + 1;
            const int ktmax = (l0 >> 4) + 1;
            const int ofs0 = OffF(l0);
            const int ofs1 = (l1 < L_NUM) ? OffF(l1) : OffF(l0);

            // rowset0 MMA (chained 3-term bf16 split into single accumulators)
            {
                float a0[4] = {0,0,0,0}, a1[4] = {0,0,0,0};
                #pragma unroll
                for (int kt = 0; kt < 4; kt++) {
                    if (kt < ktmax) {
                        unsigned long long wh0 = sWh[(ofs0 + kt) * 32 + lane];
                        unsigned long long wl0 = sWl[(ofs0 + kt) * 32 + lane];
                        unsigned long long wh1 = sWh[(ofs1 + kt) * 32 + lane];
                        unsigned long long wl1 = sWl[(ofs1 + kt) * 32 + lane];
                        mma_bf16(a0, &Ah0[kt * 4], (uint32_t)wh0, (uint32_t)(wh0 >> 32));
                        mma_bf16(a0, &Al0[kt * 4], (uint32_t)wh0, (uint32_t)(wh0 >> 32));
                        mma_bf16(a0, &Ah0[kt * 4], (uint32_t)wl0, (uint32_t)(wl0 >> 32));
                        mma_bf16(a1, &Ah0[kt * 4], (uint32_t)wh1, (uint32_t)(wh1 >> 32));
                        mma_bf16(a1, &Al0[kt * 4], (uint32_t)wh1, (uint32_t)(wh1 >> 32));
                        mma_bf16(a1, &Ah0[kt * 4], (uint32_t)wl1, (uint32_t)(wl1 >> 32));
                    }
                }
                *(float2*)&DB[r1a * D_STRIDE + c0]           = make_float2(a0[0], a0[1]);
                *(float2*)&DB[(r1a + 8) * D_STRIDE + c0]     = make_float2(a0[2], a0[3]);
                *(float2*)&DB[r1a * D_STRIDE + 8 + c0]       = make_float2(a1[0], a1[1]);
                *(float2*)&DB[(r1a + 8) * D_STRIDE + 8 + c0] = make_float2(a1[2], a1[3]);
            }
            // rowset1 MMA (same weights, fresh accumulators)
            {
                float a0[4] = {0,0,0,0}, a1[4] = {0,0,0,0};
                #pragma unroll
                for (int kt = 0; kt < 4; kt++) {
                    if (kt < ktmax) {
                        unsigned long long wh0 = sWh[(ofs0 + kt) * 32 + lane];
                        unsigned long long wl0 = sWl[(ofs0 + kt) * 32 + lane];
                        unsigned long long wh1 = sWh[(ofs1 + kt) * 32 + lane];
                        unsigned long long wl1 = sWl[(ofs1 + kt) * 32 + lane];
                        mma_bf16(a0, &Ah1[kt * 4], (uint32_t)wh0, (uint32_t)(wh0 >> 32));
                        mma_bf16(a0, &Al1[kt * 4], (uint32_t)wh0, (uint32_t)(wh0 >> 32));
                        mma_bf16(a0, &Ah1[kt * 4], (uint32_t)wl0, (uint32_t)(wl0 >> 32));
                        mma_bf16(a1, &Ah1[kt * 4], (uint32_t)wh1, (uint32_t)(wh1 >> 32));
                        mma_bf16(a1, &Al1[kt * 4], (uint32_t)wh1, (uint32_t)(wh1 >> 32));
                        mma_bf16(a1, &Ah1[kt * 4], (uint32_t)wl1, (uint32_t)(wl1 >> 32));
                    }
                }
                *(float2*)&DB[r1b * D_STRIDE + c0]           = make_float2(a0[0], a0[1]);
                *(float2*)&DB[(r1b + 8) * D_STRIDE + c0]     = make_float2(a0[2], a0[3]);
                *(float2*)&DB[r1b * D_STRIDE + 8 + c0]       = make_float2(a1[0], a1[1]);
                *(float2*)&DB[(r1b + 8) * D_STRIDE + 8 + c0] = make_float2(a1[2], a1[3]);
            }
            __syncwarp();

            // ---- epilogue: each lane handles 2 rows, layer l = 2c+parity ----
            {
                const int l = 2 * c + parity;
                if (l < L_NUM) {
                    unsigned long long ma0 = pack2(c_B2[2 * l], c_B2[2 * l + 1]);
                    unsigned long long ma1 = ma0;
                    #pragma unroll
                    for (int h = 0; h < 8; h++) {
                        float bb = c_B1[l * 8 + h];
                        unsigned long long w2 = c_W2p[l * 8 + h];
                        float hv0 = tanh_fast(Dr0[h] + bb);
                        float hv1 = tanh_fast(Dr1[h] + bb);
                        ma0 = fma2(dup2(hv0), w2, ma0);
                        ma1 = fma2(dup2(hv1), w2, ma1);
                    }
                    float mu_0, al_0, mu_1, al_1;
                    unpack2(ma0, mu_0, al_0);
                    unpack2(ma1, mu_1, al_1);
                    ld_0 += al_0; ld_1 += al_1;
                    if (c == 0 && parity == 0) {
                        XZr0[0] = XZr0[0] * e0 + mu0;
                        XZr1[0] = XZr1[0] * e0 + mu0;
                    }
                    float xn0 = XZr0[l + 1];
                    float xn1 = XZr1[l + 1];
                    XZr0[l + 1] = xn0 * exp_fast(al_0) + mu_0;
                    XZr1[l + 1] = xn1 * exp_fast(al_1) + mu_1;
                }
            }
            __syncwarp();
        }

        // ---- log-det: combine parity partials via shuffle ----
        {
            float o0 = __shfl_xor_sync(0xFFFFFFFFu, ld_0, 16);
            float o1 = __shfl_xor_sync(0xFFFFFFFFu, ld_1, 16);
            if (has_ld && parity == 0) {
                if (er0 < validRows) ld_out[base + er0] = ld_0 + o0;
                if (er1 < validRows) ld_out[base + er1] = ld_1 + o1;
            }
        }

        __syncthreads();
        // ---- coalesced z writeback ----
        {
            float2* zg = (float2*)(z_out + (size_t)base * 64);
            #pragma unroll
            for (int k = 0; k < 32; k++) {
                int idx = tid + k * THREADS;
                int row = idx >> 5, cc2 = idx & 31;
                if (row < validRows)
                    zg[idx] = *(const float2*)&XZ[row * XZ_STRIDE + 2 * cc2];
            }
        }
        __syncthreads();
    }
}

extern "C" void kernel_launch(void* const* d_in, const int* in_sizes, int n_in,
                              void* d_out, int out_size) {
    const float* x  = (const float*)d_in[0];
    const float* ip = (const float*)d_in[1];
    const float* W1 = (const float*)d_in[2];
    const float* b1 = (const float*)d_in[3];
    const float* W2 = (const float*)d_in[4];
    const float* b2 = (const float*)d_in[5];

    int B = in_sizes[0] / 64;
    float* z   = (float*)d_out;
    float* ldp = z + (size_t)B * 64;
    int has_ld = (out_size >= B * 64 + B) ? 1 : 0;
    int tiles = (B + TILE_M - 1) / TILE_M;

    int prep_n = 8192 + 512;
    prep_kernel<<<(prep_n + 255) / 256, 256>>>(W1, W2, b1, b2);

    void* p = nullptr;
    cudaGetSymbolAddress(&p, g_B1);
    cudaMemcpyToSymbolAsync(c_B1, p, sizeof(g_B1), 0, cudaMemcpyDeviceToDevice);
    cudaGetSymbolAddress(&p, g_W2p);
    cudaMemcpyToSymbolAsync(c_W2p, p, sizeof(g_W2p), 0, cudaMemcpyDeviceToDevice);
    cudaGetSymbolAddress(&p, g_B2);
    cudaMemcpyToSymbolAsync(c_B2, p, sizeof(g_B2), 0, cudaMemcpyDeviceToDevice);

    cudaFuncSetAttribute(flow_kernel, cudaFuncAttributeMaxDynamicSharedMemorySize, SMEM_BYTES);
    int grid = tiles < 148 ? tiles : 148;
    flow_kernel<<<grid, THREADS, SMEM_BYTES>>>(x, ip, z, ldp, B, tiles, has_ld);
}

// round 17
// speedup vs baseline: 3.3601x; 1.0675x over previous
#include <cuda_runtime.h>
#include <cuda_bf16.h>
#include <cstdint>

#define L_NUM  63
#define THREADS 448
#define TILE_M  448
#define NCHUNK  32            // 2 layers (n-tiles) per chunk

// triangular fragment-block prefix: blocks before layer l (layer l has l/16+1 kt-blocks)
__host__ __device__ __forceinline__ constexpr int OffF(int l) {
    int q = l >> 4, r = l & 15;
    int s = 0;
    for (int g = 0; g < q; g++) s += 16 * (g + 1);
    return s + r * (q + 1);
}
#define TOTBLK 156            // OffF(63)

__device__ unsigned long long g_Wfrag[2 * TOTBLK * 32];
__device__ float g_B1[504];
__device__ unsigned long long g_W2p[504];
__device__ float g_B2[126];

__constant__ float c_B1[504];
__constant__ unsigned long long c_W2p[504];
__constant__ float c_B2[126];

__global__ void prep_kernel(const float* __restrict__ W1, const float* __restrict__ W2,
                            const float* __restrict__ b1, const float* __restrict__ b2) {
    int i = blockIdx.x * blockDim.x + threadIdx.x;
    if (i < 8192) {                       // domain: nt(64) x kt(4) x lane(32)
        int lane = i & 31;
        int kt   = (i >> 5) & 3;
        int nt   = i >> 7;
        if (nt >= L_NUM || kt > (nt >> 4)) return;   // triangular skip
        int n  = nt * 8 + (lane >> 2);
        int k0 = kt * 16 + (lane & 3) * 2;
        int l = n >> 3, h = n & 7;
        int ks[4] = { k0, k0 + 1, k0 + 8, k0 + 9 };
        uint32_t bh[4], bl[4];
        #pragma unroll
        for (int j = 0; j < 4; j++) {
            int k = ks[j];
            float v = 0.0f;
            if (k <= l) v = W1[l * 504 + h * 63 + k];
            __nv_bfloat16 vh = __float2bfloat16_rn(v);
            float res = v - __bfloat162float(vh);
            __nv_bfloat16 vl = __float2bfloat16_rn(res);
            bh[j] = (uint32_t)__bfloat16_as_ushort(vh);
            bl[j] = (uint32_t)__bfloat16_as_ushort(vl);
        }
        uint32_t b0h = bh[0] | (bh[1] << 16), b1h = bh[2] | (bh[3] << 16);
        uint32_t b0l = bl[0] | (bl[1] << 16), b1l = bl[2] | (bl[3] << 16);
        int dst = (OffF(nt) + kt) * 32 + lane;
        g_Wfrag[dst]               = (unsigned long long)b0h | ((unsigned long long)b1h << 32);
        g_Wfrag[TOTBLK * 32 + dst] = (unsigned long long)b0l | ((unsigned long long)b1l << 32);
    } else {
        int j = i - 8192;
        if (j < 504) {
            int l = j >> 3, h = j & 7;
            float2 w = make_float2(W2[l * 16 + h], W2[l * 16 + 8 + h]);
            g_W2p[j] = *(unsigned long long*)&w;
            g_B1[j] = b1[j];
            if (j < 126) g_B2[j] = b2[j];
        }
    }
}

// ---------------- helpers ----------------
__device__ __forceinline__ void mma_bf16(float* d, const uint32_t* a, uint32_t b0, uint32_t b1) {
    asm volatile(
        "mma.sync.aligned.m16n8k16.row.col.f32.bf16.bf16.f32 "
        "{%0,%1,%2,%3}, {%4,%5,%6,%7}, {%8,%9}, {%0,%1,%2,%3};"
        : "+f"(d[0]), "+f"(d[1]), "+f"(d[2]), "+f"(d[3])
        : "r"(a[0]), "r"(a[1]), "r"(a[2]), "r"(a[3]), "r"(b0), "r"(b1));
}
__device__ __forceinline__ uint32_t packbf(float lo, float hi) {
    uint32_t r;
    asm("cvt.rn.bf16x2.f32 %0, %1, %2;" : "=r"(r) : "f"(hi), "f"(lo));
    return r;
}
__device__ __forceinline__ unsigned long long fma2(unsigned long long a,
                                                   unsigned long long b,
                                                   unsigned long long c) {
    unsigned long long d;
    asm("fma.rn.f32x2 %0, %1, %2, %3;" : "=l"(d) : "l"(a), "l"(b), "l"(c));
    return d;
}
__device__ __forceinline__ void unpack2(unsigned long long v, float& lo, float& hi) {
    asm("mov.b64 {%0, %1}, %2;" : "=f"(lo), "=f"(hi) : "l"(v));
}
__device__ __forceinline__ unsigned long long pack2(float lo, float hi) {
    unsigned long long v;
    asm("mov.b64 %0, {%1, %2};" : "=l"(v) : "f"(lo), "f"(hi));
    return v;
}
__device__ __forceinline__ unsigned long long dup2(float f) {
    unsigned long long v;
    asm("mov.b64 %0, {%1, %1};" : "=l"(v) : "f"(f));
    return v;
}
__device__ __forceinline__ float tanh_fast(float a) {
    float y; asm("tanh.approx.f32 %0, %1;" : "=f"(y) : "f"(a)); return y;
}
__device__ __forceinline__ float exp_fast(float a) {
    float y; asm("ex2.approx.f32 %0, %1;" : "=f"(y) : "f"(a * 1.442695041f)); return y;
}

// SMEM (floats): [0, 19968) frag tables; XZ 448x66; D 448x18
#define OFF_XZ_F  19968
#define XZ_STRIDE 66
#define OFF_D_F   49536
#define D_STRIDE  18
#define SMEM_BYTES 230400

__global__ __launch_bounds__(THREADS, 1)
void flow_kernel(const float* __restrict__ x,
                 const float* __restrict__ ipar,
                 float* __restrict__ z_out,
                 float* __restrict__ ld_out,
                 int B, int tiles, int has_ld)
{
    extern __shared__ char sm[];
    float* smf = (float*)sm;
    const int tid  = threadIdx.x;
    const int warp = tid >> 5;
    const int lane = tid & 31;
    const int g    = lane >> 2;
    const int tg   = lane & 3;
    const int c0   = tg * 2;
    const int rb   = warp * 32;          // this warp's 32 rows
    const int r1a  = rb + g;             // rowset0: rows r1a, r1a+8
    const int r1b  = rb + 16 + g;        // rowset1
    const int er0  = rb + (lane & 15);   // epilogue rows (one per rowset)
    const int er1  = er0 + 16;
    const int parity = lane >> 4;        // layer parity within chunk

    // ---- stage compact fragment tables once ----
    {
        const float4* ws = (const float4*)g_Wfrag;
        float4* wd = (float4*)sm;
        for (int i = tid; i < 4992; i += THREADS) wd[i] = ws[i];
    }
    const unsigned long long* sWh = (const unsigned long long*)sm;
    const unsigned long long* sWl = sWh + TOTBLK * 32;
    float* XZ = smf + OFF_XZ_F;
    float* DB = smf + OFF_D_F;

    const float mu0 = ipar[0];
    const float al0 = ipar[1];
    const float e0  = exp_fast(al0);

    for (int t = blockIdx.x; t < tiles; t += gridDim.x) {
        const int base = t * TILE_M;
        const int validRows = min(TILE_M, B - base);

        // ---- stage x tile (coalesced) ----
        {
            const float2* xg = (const float2*)(x + (size_t)base * 64);
            #pragma unroll
            for (int k = 0; k < 32; k++) {
                int idx = tid + k * THREADS;       // 0 .. 448*32-1
                int row = idx >> 5, cc2 = idx & 31;
                if (row < validRows)
                    *(float2*)&XZ[row * XZ_STRIDE + 2 * cc2] = xg[idx];
            }
        }
        __syncthreads();

        // ---- build A fragments for both rowsets (bf16 split) ----
        uint32_t Ah0[16], Al0[16], Ah1[16], Al1[16];
        #pragma unroll
        for (int rs = 0; rs < 2; rs++) {
            const int r1 = rb + rs * 16 + g;
            uint32_t* Ah = rs ? Ah1 : Ah0;
            uint32_t* Al = rs ? Al1 : Al0;
            #pragma unroll
            for (int kt = 0; kt < 4; kt++) {
                int kb = kt * 16;
                float2 p[4];
                p[0] = *(const float2*)&XZ[r1 * XZ_STRIDE + kb + c0];
                p[1] = *(const float2*)&XZ[(r1 + 8) * XZ_STRIDE + kb + c0];
                p[2] = *(const float2*)&XZ[r1 * XZ_STRIDE + kb + c0 + 8];
                p[3] = *(const float2*)&XZ[(r1 + 8) * XZ_STRIDE + kb + c0 + 8];
                #pragma unroll
                for (int j = 0; j < 4; j++) {
                    uint32_t hbits = packbf(p[j].x, p[j].y);
                    float rx = p[j].x - __uint_as_float(hbits << 16);
                    float ry = p[j].y - __uint_as_float(hbits & 0xFFFF0000u);
                    Ah[kt * 4 + j] = hbits;
                    Al[kt * 4 + j] = packbf(rx, ry);
                }
            }
        }

        float ld_0 = (parity == 0) ? al0 : 0.0f;
        float ld_1 = (parity == 0) ? al0 : 0.0f;
        float* XZr0 = XZ + er0 * XZ_STRIDE;
        float* XZr1 = XZ + er1 * XZ_STRIDE;
        const float* Dr0 = DB + er0 * D_STRIDE + parity * 8;
        const float* Dr1 = DB + er1 * D_STRIDE + parity * 8;

        // ---- chunk loop: 2 layers per chunk, warp-private, weights loaded ONCE per kt ----
        #pragma unroll
        for (int c = 0; c < NCHUNK; c++) {
            const int l0 = 2 * c, l1 = 2 * c + 1;
            const int ktmax = (l0 >> 4) + 1;
            const int ofs0 = OffF(l0);
            const int ofs1 = (l1 < L_NUM) ? OffF(l1) : OffF(l0);

            float a0[4] = {0,0,0,0}, a1[4] = {0,0,0,0};   // rowset0: layers l0, l1
            float b0[4] = {0,0,0,0}, b1v[4] = {0,0,0,0};  // rowset1: layers l0, l1
            #pragma unroll
            for (int kt = 0; kt < 4; kt++) {
                if (kt < ktmax) {
                    // shared weight loads: once per kt, feed both rowsets
                    unsigned long long wh0 = sWh[(ofs0 + kt) * 32 + lane];
                    unsigned long long wl0 = sWl[(ofs0 + kt) * 32 + lane];
                    unsigned long long wh1 = sWh[(ofs1 + kt) * 32 + lane];
                    unsigned long long wl1 = sWl[(ofs1 + kt) * 32 + lane];
                    uint32_t wh0a = (uint32_t)wh0, wh0b = (uint32_t)(wh0 >> 32);
                    uint32_t wl0a = (uint32_t)wl0, wl0b = (uint32_t)(wl0 >> 32);
                    uint32_t wh1a = (uint32_t)wh1, wh1b = (uint32_t)(wh1 >> 32);
                    uint32_t wl1a = (uint32_t)wl1, wl1b = (uint32_t)(wl1 >> 32);
                    // rowset0
                    mma_bf16(a0,  &Ah0[kt * 4], wh0a, wh0b);
                    mma_bf16(a0,  &Al0[kt * 4], wh0a, wh0b);
                    mma_bf16(a0,  &Ah0[kt * 4], wl0a, wl0b);
                    mma_bf16(a1,  &Ah0[kt * 4], wh1a, wh1b);
                    mma_bf16(a1,  &Al0[kt * 4], wh1a, wh1b);
                    mma_bf16(a1,  &Ah0[kt * 4], wl1a, wl1b);
                    // rowset1 (same weights)
                    mma_bf16(b0,  &Ah1[kt * 4], wh0a, wh0b);
                    mma_bf16(b0,  &Al1[kt * 4], wh0a, wh0b);
                    mma_bf16(b0,  &Ah1[kt * 4], wl0a, wl0b);
                    mma_bf16(b1v, &Ah1[kt * 4], wh1a, wh1b);
                    mma_bf16(b1v, &Al1[kt * 4], wh1a, wh1b);
                    mma_bf16(b1v, &Ah1[kt * 4], wl1a, wl1b);
                }
            }
            *(float2*)&DB[r1a * D_STRIDE + c0]           = make_float2(a0[0], a0[1]);
            *(float2*)&DB[(r1a + 8) * D_STRIDE + c0]     = make_float2(a0[2], a0[3]);
            *(float2*)&DB[r1a * D_STRIDE + 8 + c0]       = make_float2(a1[0], a1[1]);
            *(float2*)&DB[(r1a + 8) * D_STRIDE + 8 + c0] = make_float2(a1[2], a1[3]);
            *(float2*)&DB[r1b * D_STRIDE + c0]           = make_float2(b0[0], b0[1]);
            *(float2*)&DB[(r1b + 8) * D_STRIDE + c0]     = make_float2(b0[2], b0[3]);
            *(float2*)&DB[r1b * D_STRIDE + 8 + c0]       = make_float2(b1v[0], b1v[1]);
            *(float2*)&DB[(r1b + 8) * D_STRIDE + 8 + c0] = make_float2(b1v[2], b1v[3]);
            __syncwarp();

            // ---- epilogue: each lane handles 2 rows, layer l = 2c+parity ----
            {
                const int l = 2 * c + parity;
                if (l < L_NUM) {
                    unsigned long long ma0 = pack2(c_B2[2 * l], c_B2[2 * l + 1]);
                    unsigned long long ma1 = ma0;
                    #pragma unroll
                    for (int h = 0; h < 8; h++) {
                        float bb = c_B1[l * 8 + h];
                        unsigned long long w2 = c_W2p[l * 8 + h];
                        float hv0 = tanh_fast(Dr0[h] + bb);
                        float hv1 = tanh_fast(Dr1[h] + bb);
                        ma0 = fma2(dup2(hv0), w2, ma0);
                        ma1 = fma2(dup2(hv1), w2, ma1);
                    }
                    float mu_0, al_0, mu_1, al_1;
                    unpack2(ma0, mu_0, al_0);
                    unpack2(ma1, mu_1, al_1);
                    ld_0 += al_0; ld_1 += al_1;
                    if (c == 0 && parity == 0) {
                        XZr0[0] = XZr0[0] * e0 + mu0;
                        XZr1[0] = XZr1[0] * e0 + mu0;
                    }
                    float xn0 = XZr0[l + 1];
                    float xn1 = XZr1[l + 1];
                    XZr0[l + 1] = xn0 * exp_fast(al_0) + mu_0;
                    XZr1[l + 1] = xn1 * exp_fast(al_1) + mu_1;
                }
            }
            __syncwarp();
        }

        // ---- log-det: combine parity partials via shuffle ----
        {
            float o0 = __shfl_xor_sync(0xFFFFFFFFu, ld_0, 16);
            float o1 = __shfl_xor_sync(0xFFFFFFFFu, ld_1, 16);
            if (has_ld && parity == 0) {
                if (er0 < validRows) ld_out[base + er0] = ld_0 + o0;
                if (er1 < validRows) ld_out[base + er1] = ld_1 + o1;
            }
        }

        __syncthreads();
        // ---- coalesced z writeback ----
        {
            float2* zg = (float2*)(z_out + (size_t)base * 64);
            #pragma unroll
            for (int k = 0; k < 32; k++) {
                int idx = tid + k * THREADS;
                int row = idx >> 5, cc2 = idx & 31;
                if (row < validRows)
                    zg[idx] = *(const float2*)&XZ[row * XZ_STRIDE + 2 * cc2];
            }
        }
        __syncthreads();
    }
}

extern "C" void kernel_launch(void* const* d_in, const int* in_sizes, int n_in,
                              void* d_out, int out_size) {
    const float* x  = (const float*)d_in[0];
    const float* ip = (const float*)d_in[1];
    const float* W1 = (const float*)d_in[2];
    const float* b1 = (const float*)d_in[3];
    const float* W2 = (const float*)d_in[4];
    const float* b2 = (const float*)d_in[5];

    int B = in_sizes[0] / 64;
    float* z   = (float*)d_out;
    float* ldp = z + (size_t)B * 64;
    int has_ld = (out_size >= B * 64 + B) ? 1 : 0;
    int tiles = (B + TILE_M - 1) / TILE_M;

    int prep_n = 8192 + 512;
    prep_kernel<<<(prep_n + 255) / 256, 256>>>(W1, W2, b1, b2);

    void* p = nullptr;
    cudaGetSymbolAddress(&p, g_B1);
    cudaMemcpyToSymbolAsync(c_B1, p, sizeof(g_B1), 0, cudaMemcpyDeviceToDevice);
    cudaGetSymbolAddress(&p, g_W2p);
    cudaMemcpyToSymbolAsync(c_W2p, p, sizeof(g_W2p), 0, cudaMemcpyDeviceToDevice);
    cudaGetSymbolAddress(&p, g_B2);
    cudaMemcpyToSymbolAsync(c_B2, p, sizeof(g_B2), 0, cudaMemcpyDeviceToDevice);

    cudaFuncSetAttribute(flow_kernel, cudaFuncAttributeMaxDynamicSharedMemorySize, SMEM_BYTES);
    int grid = tiles < 148 ? tiles : 148;
    flow_kernel<<<grid, THREADS, SMEM_BYTES>>>(x, ip, z, ldp, B, tiles, has_ld);
}